// round 5
// baseline (speedup 1.0000x reference)
#include <cuda_runtime.h>
#include <cuda_bf16.h>
#include <stdint.h>
#include <math.h>

#define BB 4
#define SS 2048
#define DD 1024
#define M1 (BB*SS)

// ---------------------------------------------------------------------------
// Scratch (device globals). hi/lo bf16 stored as SEPARATE planes.
// ---------------------------------------------------------------------------
__device__ __nv_bfloat16 g_xh [(size_t)M1*DD],  g_xl [(size_t)M1*DD];
__device__ __nv_bfloat16 g_Wqh[(size_t)DD*DD],  g_Wql[(size_t)DD*DD];
__device__ __nv_bfloat16 g_Wkh[(size_t)DD*DD],  g_Wkl[(size_t)DD*DD];
__device__ __nv_bfloat16 g_Wvh[(size_t)DD*DD],  g_Wvl[(size_t)DD*DD];
__device__ __nv_bfloat16 g_Qh [(size_t)M1*DD],  g_Ql [(size_t)M1*DD];
__device__ __nv_bfloat16 g_Kh [(size_t)M1*DD],  g_Kl [(size_t)M1*DD];
__device__ __nv_bfloat16 g_Vth[(size_t)BB*DD*SS], g_Vtl[(size_t)BB*DD*SS]; // [b][d][s]
__device__ float         g_S  [(size_t)BB*SS*SS];
__device__ __nv_bfloat16 g_Ph [(size_t)BB*SS*SS], g_Pl [(size_t)BB*SS*SS];

// ---------------------------------------------------------------------------
__device__ __forceinline__ uint32_t s2u(const void* p){
    uint32_t a;
    asm("{ .reg .u64 t; cvta.to.shared.u64 t, %1; cvt.u32.u64 %0, t; }" : "=r"(a) : "l"(p));
    return a;
}
__device__ __forceinline__ void split2(float v, __nv_bfloat16& h, __nv_bfloat16& l){
    h = __float2bfloat16(v);
    l = __float2bfloat16(v - __bfloat162float(h));
}

#define LDSM4(r0,r1,r2,r3,a) \
    asm volatile("ldmatrix.sync.aligned.m8n8.x4.shared.b16 {%0,%1,%2,%3}, [%4];" \
        : "=r"(r0),"=r"(r1),"=r"(r2),"=r"(r3) : "r"(a))

#define MMA16816(c,a0,a1,a2,a3,b0,b1) \
    asm volatile("mma.sync.aligned.m16n8k16.row.col.f32.bf16.bf16.f32 " \
        "{%0,%1,%2,%3},{%4,%5,%6,%7},{%8,%9},{%0,%1,%2,%3};" \
        : "+f"((c)[0]),"+f"((c)[1]),"+f"((c)[2]),"+f"((c)[3]) \
        : "r"(a0),"r"(a1),"r"(a2),"r"(a3),"r"(b0),"r"(b1))

#define CP16(dst,src) \
    asm volatile("cp.async.cg.shared.global [%0], [%1], 16;" :: "r"(dst), "l"(src) : "memory")
#define CP_COMMIT() asm volatile("cp.async.commit_group;" ::: "memory")
#define CP_WAIT1()  asm volatile("cp.async.wait_group 1;" ::: "memory")
#define CP_WAIT0()  asm volatile("cp.async.wait_group 0;" ::: "memory")

// ---------------------------------------------------------------------------
// HMMA GEMM, C[m,n] = sum_k A[m,k]*B[n,k]; A/B are hi+lo bf16 planes, K-major.
// CTA 128x128, 256 threads = 8 warps (4 in m x 2 in n), warp tile 32x64.
// KC=64, 3-stage cp.async; ldmatrix fragments double-buffered across ks-steps
// so LDSM latency hides behind the 48-MMA burst of the previous step.
// 3 products: Ah*Bh + Al*Bh + Ah*Bl, fp32 accum.
// ---------------------------------------------------------------------------
#define KC 64
#define PITCHB 144
#define TILEB (128*PITCHB)            // 18432
#define STAGEB (4*TILEB)              // Ah,Al,Bh,Bl = 73728
#define SMEMSZ (3*STAGEB)             // 221184

template<int EPI>
__global__ __launch_bounds__(256, 1)
void gemm_t(const __nv_bfloat16* __restrict__ Ah, const __nv_bfloat16* __restrict__ Al,
            const __nv_bfloat16* __restrict__ Bh, const __nv_bfloat16* __restrict__ Bl,
            const float* __restrict__ bias, void* __restrict__ C0, void* __restrict__ C1,
            int Kg, int ldc, long sA, long sB, long sC)
{
    extern __shared__ __align__(128) char dsm[];
    const int tid = threadIdx.x;
    const int wid = tid >> 5, lane = tid & 31;
    const int warp_m = wid & 3, warp_n = wid >> 2;   // 4 x 2 warps
    const int m0 = blockIdx.y * 128, n0 = blockIdx.x * 128, z = blockIdx.z;

    const __nv_bfloat16* pl[4] = {
        Ah + (size_t)z * sA + (size_t)m0 * Kg,
        Al + (size_t)z * sA + (size_t)m0 * Kg,
        Bh + (size_t)z * sB + (size_t)n0 * Kg,
        Bl + (size_t)z * sB + (size_t)n0 * Kg };

    const uint32_t sb = s2u(dsm);

    // cp.async: 16 x 16B per thread per chunk; i-blocks of 4 map to one tile.
    auto issue = [&](int c, int s){
        const int kc0 = c * KC;
        const uint32_t st = sb + s * STAGEB;
        #pragma unroll
        for (int i = 0; i < 16; i++){
            int idx = tid + i * 256;
            int t = idx >> 10;                // tile: 0..3
            int rem = idx & 1023;
            int r = rem >> 3, q = rem & 7;    // row 0..127, 16B col 0..7
            const void* src = pl[t] + (size_t)r * Kg + kc0 + q * 8;
            CP16(st + t * TILEB + r * PITCHB + q * 16, src);
        }
        CP_COMMIT();
    };

    const int lrow = lane & 15, lph = lane >> 4;
    uint32_t aA[2], aB[4];
    #pragma unroll
    for (int f = 0; f < 2; f++)
        aA[f] = sb + (warp_m*32 + f*16 + lrow) * PITCHB + lph * 16;
    #pragma unroll
    for (int p = 0; p < 4; p++)
        aB[p] = sb + 2*TILEB + (warp_n*64 + p*16 + lrow) * PITCHB + lph * 16;

    float acc[2][8][4];
    #pragma unroll
    for (int f = 0; f < 2; f++)
        #pragma unroll
        for (int b = 0; b < 8; b++)
            #pragma unroll
            for (int j = 0; j < 4; j++) acc[f][b][j] = 0.f;

    // double-buffered fragments
    uint32_t ah[2][2][4], al[2][2][4], bh[2][4][4], bl[2][4][4];

    auto load_frags = [&](int fb, uint32_t so, uint32_t ko){
        #pragma unroll
        for (int f = 0; f < 2; f++){
            LDSM4(ah[fb][f][0],ah[fb][f][1],ah[fb][f][2],ah[fb][f][3], aA[f] + so + ko);
            LDSM4(al[fb][f][0],al[fb][f][1],al[fb][f][2],al[fb][f][3], aA[f] + so + ko + TILEB);
        }
        #pragma unroll
        for (int p = 0; p < 4; p++){
            LDSM4(bh[fb][p][0],bh[fb][p][1],bh[fb][p][2],bh[fb][p][3], aB[p] + so + ko);
            LDSM4(bl[fb][p][0],bl[fb][p][1],bl[fb][p][2],bl[fb][p][3], aB[p] + so + ko + TILEB);
        }
    };
    auto mma_step = [&](int fb){
        #pragma unroll
        for (int f = 0; f < 2; f++)
            #pragma unroll
            for (int p = 0; p < 4; p++)
                #pragma unroll
                for (int nb = 0; nb < 2; nb++){
                    float* cc = acc[f][p*2+nb];
                    MMA16816(cc, ah[fb][f][0],ah[fb][f][1],ah[fb][f][2],ah[fb][f][3],
                             bh[fb][p][nb], bh[fb][p][nb+2]);
                    MMA16816(cc, al[fb][f][0],al[fb][f][1],al[fb][f][2],al[fb][f][3],
                             bh[fb][p][nb], bh[fb][p][nb+2]);
                    MMA16816(cc, ah[fb][f][0],ah[fb][f][1],ah[fb][f][2],ah[fb][f][3],
                             bl[fb][p][nb], bl[fb][p][nb+2]);
                }
    };

    const int NC = Kg / KC;
    issue(0, 0);
    issue(1, 1);

    for (int c = 0; c < NC; c++){
        if (c < NC - 1) CP_WAIT1(); else CP_WAIT0();
        __syncthreads();
        if (c + 2 < NC) issue(c + 2, (c + 2) % 3);

        const uint32_t so = (c % 3) * STAGEB;
        load_frags(0, so, 0);
        #pragma unroll
        for (int ks = 0; ks < 4; ks++){
            if (ks < 3) load_frags((ks + 1) & 1, so, (ks + 1) * 32);
            mma_step(ks & 1);
        }
    }
    __syncthreads();

    // ---- epilogue: acc -> staging smem [128][132] fp32 -> global ----
    float* stg = (float*)dsm;
    const int erow = lane >> 2, ecol2 = (lane & 3) * 2;
    #pragma unroll
    for (int f = 0; f < 2; f++)
        #pragma unroll
        for (int p = 0; p < 4; p++)
            #pragma unroll
            for (int nb = 0; nb < 2; nb++){
                int r  = warp_m*32 + f*16 + erow;
                int cl = warp_n*64 + p*16 + nb*8 + ecol2;
                float* cc = acc[f][p*2+nb];
                *(float2*)&stg[r*132 + cl]     = make_float2(cc[0], cc[1]);
                *(float2*)&stg[(r+8)*132 + cl] = make_float2(cc[2], cc[3]);
            }
    __syncthreads();

    if (EPI == 0){
        #pragma unroll
        for (int i = 0; i < 64; i++){
            int idx = tid + i * 256;
            int j = idx & 127, m = idx >> 7;
            float v = stg[m*132 + j] + bias[n0 + j];
            __nv_bfloat16 h, l; split2(v, h, l);
            size_t o = (size_t)(m0 + m) * ldc + n0 + j;
            ((__nv_bfloat16*)C0)[o] = h;
            ((__nv_bfloat16*)C1)[o] = l;
        }
    } else if (EPI == 1){
        #pragma unroll
        for (int i = 0; i < 64; i++){
            int idx = tid + i * 256;
            int m = idx & 127, j = idx >> 7;
            float v = stg[m*132 + j] + bias[n0 + j];
            __nv_bfloat16 h, l; split2(v, h, l);
            int mg = m0 + m;
            int b  = mg >> 11, s = mg & (SS - 1);
            size_t o = ((size_t)b * DD + (n0 + j)) * SS + s;
            ((__nv_bfloat16*)C0)[o] = h;
            ((__nv_bfloat16*)C1)[o] = l;
        }
    } else {
        #pragma unroll
        for (int i = 0; i < 64; i++){
            int idx = tid + i * 256;
            int j = idx & 127, m = idx >> 7;
            ((float*)C0)[(size_t)z * sC + (size_t)(m0 + m) * ldc + n0 + j] = stg[m*132 + j];
        }
    }
}

// ---------------------------------------------------------------------------
__global__ __launch_bounds__(256)
void conv_k(const float* __restrict__ in, __nv_bfloat16* __restrict__ oh,
            __nv_bfloat16* __restrict__ ol, int n4)
{
    int i = blockIdx.x * 256 + threadIdx.x;
    if (i >= n4) return;
    float4 v = ((const float4*)in)[i];
    __nv_bfloat16 h0,h1,h2,h3,l0,l1,l2,l3;
    split2(v.x,h0,l0); split2(v.y,h1,l1); split2(v.z,h2,l2); split2(v.w,h3,l3);
    uint2 H, L;
    H.x = (uint32_t)__bfloat16_as_ushort(h0) | ((uint32_t)__bfloat16_as_ushort(h1)<<16);
    H.y = (uint32_t)__bfloat16_as_ushort(h2) | ((uint32_t)__bfloat16_as_ushort(h3)<<16);
    L.x = (uint32_t)__bfloat16_as_ushort(l0) | ((uint32_t)__bfloat16_as_ushort(l1)<<16);
    L.y = (uint32_t)__bfloat16_as_ushort(l2) | ((uint32_t)__bfloat16_as_ushort(l3)<<16);
    ((uint2*)oh)[i] = H;
    ((uint2*)ol)[i] = L;
}

// ---------------------------------------------------------------------------
__global__ __launch_bounds__(256)
void softmax_k()
{
    const size_t row = blockIdx.x;
    float* p = g_S + row * SS;
    __nv_bfloat16* ph = g_Ph + row * SS;
    __nv_bfloat16* pxl = g_Pl + row * SS;
    const int t = threadIdx.x;
    const int lane = t & 31, w = t >> 5;
    __shared__ float red[8];

    float v[8];
    float mx = -3.4e38f;
    #pragma unroll
    for (int i = 0; i < 8; i++){ v[i] = p[t + i*256]; mx = fmaxf(mx, v[i]); }
    #pragma unroll
    for (int o = 16; o; o >>= 1) mx = fmaxf(mx, __shfl_xor_sync(0xffffffffu, mx, o));
    if (lane == 0) red[w] = mx;
    __syncthreads();
    float m = red[0];
    #pragma unroll
    for (int i = 1; i < 8; i++) m = fmaxf(m, red[i]);

    float s = 0.f;
    #pragma unroll
    for (int i = 0; i < 8; i++){ v[i] = expf(v[i] - m); s += v[i]; }
    #pragma unroll
    for (int o = 16; o; o >>= 1) s += __shfl_xor_sync(0xffffffffu, s, o);
    __syncthreads();
    if (lane == 0) red[w] = s;
    __syncthreads();
    s = 0.f;
    #pragma unroll
    for (int i = 0; i < 8; i++) s += red[i];

    const float inv = 1.0f / s;
    #pragma unroll
    for (int i = 0; i < 8; i++){
        __nv_bfloat16 h, l; split2(v[i] * inv, h, l);
        ph[t + i*256] = h;
        pxl[t + i*256] = l;
    }
}

// ---------------------------------------------------------------------------
extern "C" void kernel_launch(void* const* d_in, const int* in_sizes, int n_in,
                              void* d_out, int out_size)
{
    const float* x  = (const float*)d_in[0];
    const float* Wq = (const float*)d_in[1];
    const float* bq = (const float*)d_in[2];
    const float* Wk = (const float*)d_in[3];
    const float* bk = (const float*)d_in[4];
    const float* Wv = (const float*)d_in[5];
    const float* bv = (const float*)d_in[6];
    float* out = (float*)d_out;

    __nv_bfloat16 *xh,*xl,*Wqh,*Wql,*Wkh,*Wkl,*Wvh,*Wvl,*Qh,*Ql,*Kh,*Kl,*Vth,*Vtl,*Ph,*Pl;
    float* Sp;
    cudaGetSymbolAddress((void**)&xh,  g_xh);  cudaGetSymbolAddress((void**)&xl,  g_xl);
    cudaGetSymbolAddress((void**)&Wqh, g_Wqh); cudaGetSymbolAddress((void**)&Wql, g_Wql);
    cudaGetSymbolAddress((void**)&Wkh, g_Wkh); cudaGetSymbolAddress((void**)&Wkl, g_Wkl);
    cudaGetSymbolAddress((void**)&Wvh, g_Wvh); cudaGetSymbolAddress((void**)&Wvl, g_Wvl);
    cudaGetSymbolAddress((void**)&Qh,  g_Qh);  cudaGetSymbolAddress((void**)&Ql,  g_Ql);
    cudaGetSymbolAddress((void**)&Kh,  g_Kh);  cudaGetSymbolAddress((void**)&Kl,  g_Kl);
    cudaGetSymbolAddress((void**)&Vth, g_Vth); cudaGetSymbolAddress((void**)&Vtl, g_Vtl);
    cudaGetSymbolAddress((void**)&Ph,  g_Ph);  cudaGetSymbolAddress((void**)&Pl,  g_Pl);
    cudaGetSymbolAddress((void**)&Sp,  g_S);

    cudaFuncSetAttribute(gemm_t<0>, cudaFuncAttributeMaxDynamicSharedMemorySize, SMEMSZ);
    cudaFuncSetAttribute(gemm_t<1>, cudaFuncAttributeMaxDynamicSharedMemorySize, SMEMSZ);
    cudaFuncSetAttribute(gemm_t<2>, cudaFuncAttributeMaxDynamicSharedMemorySize, SMEMSZ);

    conv_k<<<(M1*DD/4 + 255)/256, 256>>>(x,  xh,  xl,  M1*DD/4);
    conv_k<<<(DD*DD/4 + 255)/256, 256>>>(Wq, Wqh, Wql, DD*DD/4);
    conv_k<<<(DD*DD/4 + 255)/256, 256>>>(Wk, Wkh, Wkl, DD*DD/4);
    conv_k<<<(DD*DD/4 + 255)/256, 256>>>(Wv, Wvh, Wvl, DD*DD/4);

    dim3 gp(DD/128, M1/128, 1);
    gemm_t<0><<<gp, 256, SMEMSZ>>>(xh, xl, Wqh, Wql, bq, Qh,  Ql,  DD, DD, 0, 0, 0);
    gemm_t<0><<<gp, 256, SMEMSZ>>>(xh, xl, Wkh, Wkl, bk, Kh,  Kl,  DD, DD, 0, 0, 0);
    gemm_t<1><<<gp, 256, SMEMSZ>>>(xh, xl, Wvh, Wvl, bv, Vth, Vtl, DD, DD, 0, 0, 0);

    dim3 gs(SS/128, SS/128, BB);
    gemm_t<2><<<gs, 256, SMEMSZ>>>(Qh, Ql, Kh, Kl, nullptr, Sp, nullptr, DD, SS,
                                   (long)SS*DD, (long)SS*DD, (long)SS*SS);

    softmax_k<<<BB*SS, 256>>>();

    dim3 gv(DD/128, SS/128, BB);
    gemm_t<2><<<gv, 256, SMEMSZ>>>(Ph, Pl, Vth, Vtl, nullptr, out, nullptr, SS, DD,
                                   (long)SS*SS, (long)DD*SS, (long)SS*DD);
}

// round 6
// speedup vs baseline: 1.0069x; 1.0069x over previous
#include <cuda_runtime.h>
#include <cuda_fp16.h>
#include <stdint.h>
#include <math.h>

#define BB 4
#define SS 2048
#define DD 1024
#define M1 (BB*SS)

#define LSCALE 2048.0f
#define LINV   (1.0f/2048.0f)

// ---------------------------------------------------------------------------
// Scratch (device globals). fp16 hi/lo planes; lo pre-scaled by 2048.
// ---------------------------------------------------------------------------
__device__ __half g_xh [(size_t)M1*DD],  g_xl [(size_t)M1*DD];
__device__ __half g_Wqh[(size_t)DD*DD],  g_Wql[(size_t)DD*DD];
__device__ __half g_Wkh[(size_t)DD*DD],  g_Wkl[(size_t)DD*DD];
__device__ __half g_Wvh[(size_t)DD*DD],  g_Wvl[(size_t)DD*DD];
__device__ __half g_Qh [(size_t)M1*DD],  g_Ql [(size_t)M1*DD];
__device__ __half g_Kh [(size_t)M1*DD],  g_Kl [(size_t)M1*DD];
__device__ __half g_Vth[(size_t)BB*DD*SS], g_Vtl[(size_t)BB*DD*SS]; // [b][d][s]
__device__ float  g_S  [(size_t)BB*SS*SS];
__device__ __half g_Ph [(size_t)BB*SS*SS], g_Pl [(size_t)BB*SS*SS];

// ---------------------------------------------------------------------------
__device__ __forceinline__ uint32_t s2u(const void* p){
    uint32_t a;
    asm("{ .reg .u64 t; cvta.to.shared.u64 t, %1; cvt.u32.u64 %0, t; }" : "=r"(a) : "l"(p));
    return a;
}
__device__ __forceinline__ void split2h(float v, __half& h, __half& l){
    h = __float2half(v);
    l = __float2half((v - __half2float(h)) * LSCALE);
}

#define LDSM4(r0,r1,r2,r3,a) \
    asm volatile("ldmatrix.sync.aligned.m8n8.x4.shared.b16 {%0,%1,%2,%3}, [%4];" \
        : "=r"(r0),"=r"(r1),"=r"(r2),"=r"(r3) : "r"(a))

// hi product: fp32 accumulate
#define MMAF32(c,a0,a1,a2,a3,b0,b1) \
    asm volatile("mma.sync.aligned.m16n8k16.row.col.f32.f16.f16.f32 " \
        "{%0,%1,%2,%3},{%4,%5,%6,%7},{%8,%9},{%0,%1,%2,%3};" \
        : "+f"((c)[0]),"+f"((c)[1]),"+f"((c)[2]),"+f"((c)[3]) \
        : "r"(a0),"r"(a1),"r"(a2),"r"(a3),"r"(b0),"r"(b1))

// lo products: fp16 accumulate (2 regs = 4 halves)
#define MMAF16(c,a0,a1,a2,a3,b0,b1) \
    asm volatile("mma.sync.aligned.m16n8k16.row.col.f16.f16.f16.f16 " \
        "{%0,%1},{%2,%3,%4,%5},{%6,%7},{%0,%1};" \
        : "+r"((c)[0]),"+r"((c)[1]) \
        : "r"(a0),"r"(a1),"r"(a2),"r"(a3),"r"(b0),"r"(b1))

#define CP16(dst,src) \
    asm volatile("cp.async.cg.shared.global [%0], [%1], 16;" :: "r"(dst), "l"(src) : "memory")
#define CP_COMMIT() asm volatile("cp.async.commit_group;" ::: "memory")
#define CP_WAIT1()  asm volatile("cp.async.wait_group 1;" ::: "memory")
#define CP_WAIT0()  asm volatile("cp.async.wait_group 0;" ::: "memory")

// ---------------------------------------------------------------------------
// HMMA GEMM, C[m,n] = sum_k A[m,k]*B[n,k]; A/B are fp16 hi+lo planes (lo
// pre-scaled by 2048), K-major. CTA 128x128, 256 thr = 8 warps (4m x 2n),
// warp tile 32x64, KC=64, 3-stage cp.async, frag double-buffering.
// Per k16: hi*hi -> fp32 acc;  lo*hi + hi*lo -> shared fp16 acc.
// Final: C = acc_hi + float(acc_lo)/2048.
// ---------------------------------------------------------------------------
#define KC 64
#define PITCHB 144
#define TILEB (128*PITCHB)
#define STAGEB (4*TILEB)
#define SMEMSZ (3*STAGEB)

template<int EPI>
__global__ __launch_bounds__(256, 1)
void gemm_t(const __half* __restrict__ Ah, const __half* __restrict__ Al,
            const __half* __restrict__ Bh, const __half* __restrict__ Bl,
            const float* __restrict__ bias, void* __restrict__ C0, void* __restrict__ C1,
            int Kg, int ldc, long sA, long sB, long sC)
{
    extern __shared__ __align__(128) char dsm[];
    const int tid = threadIdx.x;
    const int wid = tid >> 5, lane = tid & 31;
    const int warp_m = wid & 3, warp_n = wid >> 2;
    const int m0 = blockIdx.y * 128, n0 = blockIdx.x * 128, z = blockIdx.z;

    const __half* pl[4] = {
        Ah + (size_t)z * sA + (size_t)m0 * Kg,
        Al + (size_t)z * sA + (size_t)m0 * Kg,
        Bh + (size_t)z * sB + (size_t)n0 * Kg,
        Bl + (size_t)z * sB + (size_t)n0 * Kg };

    const uint32_t sb = s2u(dsm);

    auto issue = [&](int c, int s){
        const int kc0 = c * KC;
        const uint32_t st = sb + s * STAGEB;
        #pragma unroll
        for (int i = 0; i < 16; i++){
            int idx = tid + i * 256;
            int t = idx >> 10;
            int rem = idx & 1023;
            int r = rem >> 3, q = rem & 7;
            const void* src = pl[t] + (size_t)r * Kg + kc0 + q * 8;
            CP16(st + t * TILEB + r * PITCHB + q * 16, src);
        }
        CP_COMMIT();
    };

    const int lrow = lane & 15, lph = lane >> 4;
    uint32_t aA[2], aB[4];
    #pragma unroll
    for (int f = 0; f < 2; f++)
        aA[f] = sb + (warp_m*32 + f*16 + lrow) * PITCHB + lph * 16;
    #pragma unroll
    for (int p = 0; p < 4; p++)
        aB[p] = sb + 2*TILEB + (warp_n*64 + p*16 + lrow) * PITCHB + lph * 16;

    float acc[2][8][4];
    uint32_t accl[2][8][2];
    #pragma unroll
    for (int f = 0; f < 2; f++)
        #pragma unroll
        for (int b = 0; b < 8; b++){
            #pragma unroll
            for (int j = 0; j < 4; j++) acc[f][b][j] = 0.f;
            accl[f][b][0] = 0u; accl[f][b][1] = 0u;
        }

    uint32_t ah[2][2][4], al[2][2][4], bh[2][4][4], bl[2][4][4];

    auto load_frags = [&](int fb, uint32_t so, uint32_t ko){
        #pragma unroll
        for (int f = 0; f < 2; f++){
            LDSM4(ah[fb][f][0],ah[fb][f][1],ah[fb][f][2],ah[fb][f][3], aA[f] + so + ko);
            LDSM4(al[fb][f][0],al[fb][f][1],al[fb][f][2],al[fb][f][3], aA[f] + so + ko + TILEB);
        }
        #pragma unroll
        for (int p = 0; p < 4; p++){
            LDSM4(bh[fb][p][0],bh[fb][p][1],bh[fb][p][2],bh[fb][p][3], aB[p] + so + ko);
            LDSM4(bl[fb][p][0],bl[fb][p][1],bl[fb][p][2],bl[fb][p][3], aB[p] + so + ko + TILEB);
        }
    };
    auto mma_step = [&](int fb){
        #pragma unroll
        for (int f = 0; f < 2; f++)
            #pragma unroll
            for (int p = 0; p < 4; p++)
                #pragma unroll
                for (int nb = 0; nb < 2; nb++){
                    float*    cc = acc [f][p*2+nb];
                    uint32_t* cl = accl[f][p*2+nb];
                    MMAF32(cc, ah[fb][f][0],ah[fb][f][1],ah[fb][f][2],ah[fb][f][3],
                           bh[fb][p][nb], bh[fb][p][nb+2]);
                    MMAF16(cl, al[fb][f][0],al[fb][f][1],al[fb][f][2],al[fb][f][3],
                           bh[fb][p][nb], bh[fb][p][nb+2]);
                    MMAF16(cl, ah[fb][f][0],ah[fb][f][1],ah[fb][f][2],ah[fb][f][3],
                           bl[fb][p][nb], bl[fb][p][nb+2]);
                }
    };

    const int NC = Kg / KC;
    issue(0, 0);
    issue(1, 1);

    for (int c = 0; c < NC; c++){
        if (c < NC - 1) CP_WAIT1(); else CP_WAIT0();
        __syncthreads();
        if (c + 2 < NC) issue(c + 2, (c + 2) % 3);

        const uint32_t so = (c % 3) * STAGEB;
        load_frags(0, so, 0);
        #pragma unroll
        for (int ks = 0; ks < 4; ks++){
            if (ks < 3) load_frags((ks + 1) & 1, so, (ks + 1) * 32);
            mma_step(ks & 1);
        }
    }
    __syncthreads();

    // ---- epilogue: merge hi + lo/2048 -> staging smem [128][132] -> global ----
    float* stg = (float*)dsm;
    const int erow = lane >> 2, ecol2 = (lane & 3) * 2;
    #pragma unroll
    for (int f = 0; f < 2; f++)
        #pragma unroll
        for (int p = 0; p < 4; p++)
            #pragma unroll
            for (int nb = 0; nb < 2; nb++){
                int r  = warp_m*32 + f*16 + erow;
                int cl = warp_n*64 + p*16 + nb*8 + ecol2;
                float*    cc = acc [f][p*2+nb];
                uint32_t* lr = accl[f][p*2+nb];
                float2 w0 = __half22float2(*reinterpret_cast<__half2*>(&lr[0]));
                float2 w1 = __half22float2(*reinterpret_cast<__half2*>(&lr[1]));
                *(float2*)&stg[r*132 + cl] =
                    make_float2(cc[0] + w0.x*LINV, cc[1] + w0.y*LINV);
                *(float2*)&stg[(r+8)*132 + cl] =
                    make_float2(cc[2] + w1.x*LINV, cc[3] + w1.y*LINV);
            }
    __syncthreads();

    if (EPI == 0){
        #pragma unroll
        for (int i = 0; i < 64; i++){
            int idx = tid + i * 256;
            int j = idx & 127, m = idx >> 7;
            float v = stg[m*132 + j] + bias[n0 + j];
            __half h, l; split2h(v, h, l);
            size_t o = (size_t)(m0 + m) * ldc + n0 + j;
            ((__half*)C0)[o] = h;
            ((__half*)C1)[o] = l;
        }
    } else if (EPI == 1){
        #pragma unroll
        for (int i = 0; i < 64; i++){
            int idx = tid + i * 256;
            int m = idx & 127, j = idx >> 7;
            float v = stg[m*132 + j] + bias[n0 + j];
            __half h, l; split2h(v, h, l);
            int mg = m0 + m;
            int b  = mg >> 11, s = mg & (SS - 1);
            size_t o = ((size_t)b * DD + (n0 + j)) * SS + s;
            ((__half*)C0)[o] = h;
            ((__half*)C1)[o] = l;
        }
    } else {
        #pragma unroll
        for (int i = 0; i < 64; i++){
            int idx = tid + i * 256;
            int j = idx & 127, m = idx >> 7;
            ((float*)C0)[(size_t)z * sC + (size_t)(m0 + m) * ldc + n0 + j] = stg[m*132 + j];
        }
    }
}

// ---------------------------------------------------------------------------
__global__ __launch_bounds__(256)
void conv_k(const float* __restrict__ in, __half* __restrict__ oh,
            __half* __restrict__ ol, int n4)
{
    int i = blockIdx.x * 256 + threadIdx.x;
    if (i >= n4) return;
    float4 v = ((const float4*)in)[i];
    __half h0,h1,h2,h3,l0,l1,l2,l3;
    split2h(v.x,h0,l0); split2h(v.y,h1,l1); split2h(v.z,h2,l2); split2h(v.w,h3,l3);
    __half2* H = (__half2*)oh;
    __half2* L = (__half2*)ol;
    H[i*2+0] = __halves2half2(h0,h1);
    H[i*2+1] = __halves2half2(h2,h3);
    L[i*2+0] = __halves2half2(l0,l1);
    L[i*2+1] = __halves2half2(l2,l3);
}

// ---------------------------------------------------------------------------
__global__ __launch_bounds__(256)
void softmax_k()
{
    const size_t row = blockIdx.x;
    float* p = g_S + row * SS;
    __half* ph = g_Ph + row * SS;
    __half* pll = g_Pl + row * SS;
    const int t = threadIdx.x;
    const int lane = t & 31, w = t >> 5;
    __shared__ float red[8];

    float v[8];
    float mx = -3.4e38f;
    #pragma unroll
    for (int i = 0; i < 8; i++){ v[i] = p[t + i*256]; mx = fmaxf(mx, v[i]); }
    #pragma unroll
    for (int o = 16; o; o >>= 1) mx = fmaxf(mx, __shfl_xor_sync(0xffffffffu, mx, o));
    if (lane == 0) red[w] = mx;
    __syncthreads();
    float m = red[0];
    #pragma unroll
    for (int i = 1; i < 8; i++) m = fmaxf(m, red[i]);

    float s = 0.f;
    #pragma unroll
    for (int i = 0; i < 8; i++){ v[i] = expf(v[i] - m); s += v[i]; }
    #pragma unroll
    for (int o = 16; o; o >>= 1) s += __shfl_xor_sync(0xffffffffu, s, o);
    __syncthreads();
    if (lane == 0) red[w] = s;
    __syncthreads();
    s = 0.f;
    #pragma unroll
    for (int i = 0; i < 8; i++) s += red[i];

    const float inv = 1.0f / s;
    #pragma unroll
    for (int i = 0; i < 8; i++){
        __half h, l; split2h(v[i] * inv, h, l);
        ph[t + i*256] = h;
        pll[t + i*256] = l;
    }
}

// ---------------------------------------------------------------------------
extern "C" void kernel_launch(void* const* d_in, const int* in_sizes, int n_in,
                              void* d_out, int out_size)
{
    const float* x  = (const float*)d_in[0];
    const float* Wq = (const float*)d_in[1];
    const float* bq = (const float*)d_in[2];
    const float* Wk = (const float*)d_in[3];
    const float* bk = (const float*)d_in[4];
    const float* Wv = (const float*)d_in[5];
    const float* bv = (const float*)d_in[6];
    float* out = (float*)d_out;

    __half *xh,*xl,*Wqh,*Wql,*Wkh,*Wkl,*Wvh,*Wvl,*Qh,*Ql,*Kh,*Kl,*Vth,*Vtl,*Ph,*Pl;
    float* Sp;
    cudaGetSymbolAddress((void**)&xh,  g_xh);  cudaGetSymbolAddress((void**)&xl,  g_xl);
    cudaGetSymbolAddress((void**)&Wqh, g_Wqh); cudaGetSymbolAddress((void**)&Wql, g_Wql);
    cudaGetSymbolAddress((void**)&Wkh, g_Wkh); cudaGetSymbolAddress((void**)&Wkl, g_Wkl);
    cudaGetSymbolAddress((void**)&Wvh, g_Wvh); cudaGetSymbolAddress((void**)&Wvl, g_Wvl);
    cudaGetSymbolAddress((void**)&Qh,  g_Qh);  cudaGetSymbolAddress((void**)&Ql,  g_Ql);
    cudaGetSymbolAddress((void**)&Kh,  g_Kh);  cudaGetSymbolAddress((void**)&Kl,  g_Kl);
    cudaGetSymbolAddress((void**)&Vth, g_Vth); cudaGetSymbolAddress((void**)&Vtl, g_Vtl);
    cudaGetSymbolAddress((void**)&Ph,  g_Ph);  cudaGetSymbolAddress((void**)&Pl,  g_Pl);
    cudaGetSymbolAddress((void**)&Sp,  g_S);

    cudaFuncSetAttribute(gemm_t<0>, cudaFuncAttributeMaxDynamicSharedMemorySize, SMEMSZ);
    cudaFuncSetAttribute(gemm_t<1>, cudaFuncAttributeMaxDynamicSharedMemorySize, SMEMSZ);
    cudaFuncSetAttribute(gemm_t<2>, cudaFuncAttributeMaxDynamicSharedMemorySize, SMEMSZ);

    conv_k<<<(M1*DD/4 + 255)/256, 256>>>(x,  xh,  xl,  M1*DD/4);
    conv_k<<<(DD*DD/4 + 255)/256, 256>>>(Wq, Wqh, Wql, DD*DD/4);
    conv_k<<<(DD*DD/4 + 255)/256, 256>>>(Wk, Wkh, Wkl, DD*DD/4);
    conv_k<<<(DD*DD/4 + 255)/256, 256>>>(Wv, Wvh, Wvl, DD*DD/4);

    dim3 gp(DD/128, M1/128, 1);
    gemm_t<0><<<gp, 256, SMEMSZ>>>(xh, xl, Wqh, Wql, bq, Qh,  Ql,  DD, DD, 0, 0, 0);
    gemm_t<0><<<gp, 256, SMEMSZ>>>(xh, xl, Wkh, Wkl, bk, Kh,  Kl,  DD, DD, 0, 0, 0);
    gemm_t<1><<<gp, 256, SMEMSZ>>>(xh, xl, Wvh, Wvl, bv, Vth, Vtl, DD, DD, 0, 0, 0);

    dim3 gs(SS/128, SS/128, BB);
    gemm_t<2><<<gs, 256, SMEMSZ>>>(Qh, Ql, Kh, Kl, nullptr, Sp, nullptr, DD, SS,
                                   (long)SS*DD, (long)SS*DD, (long)SS*SS);

    softmax_k<<<BB*SS, 256>>>();

    dim3 gv(DD/128, SS/128, BB);
    gemm_t<2><<<gv, 256, SMEMSZ>>>(Ph, Pl, Vth, Vtl, nullptr, out, nullptr, SS, DD,
                                   (long)SS*SS, (long)DD*SS, (long)SS*DD);
}

// round 8
// speedup vs baseline: 1.5695x; 1.5587x over previous
#include <cuda_runtime.h>
#include <cuda_fp16.h>
#include <stdint.h>
#include <math.h>

#define BB 4
#define SS 2048
#define DD 1024
#define M1 (BB*SS)

#define LSCALE 2048.0f
#define LINV   (1.0f/2048.0f)

// ---------------------------------------------------------------------------
// Scratch (device globals).
// ---------------------------------------------------------------------------
__device__ __half g_xh [(size_t)M1*DD],  g_xl [(size_t)M1*DD];
__device__ __half g_Wqh[(size_t)DD*DD],  g_Wql[(size_t)DD*DD];
__device__ __half g_Wkh[(size_t)DD*DD],  g_Wkl[(size_t)DD*DD];
__device__ __half g_Wvh[(size_t)DD*DD],  g_Wvl[(size_t)DD*DD];
__device__ float  g_Qf [(size_t)M1*DD];        // fp32 Q (for exact refine)
__device__ float  g_Kf [(size_t)M1*DD];        // fp32 K
__device__ float  g_Vf [(size_t)M1*DD];        // fp32 V (gathered in attn)
__device__ __half g_Qh [(size_t)M1*DD];        // fp16 Q (cheap scores)
__device__ __half g_Kh [(size_t)M1*DD];        // fp16 K
__device__ float  g_S  [(size_t)BB*SS*SS];     // approximate logits

// ---------------------------------------------------------------------------
__device__ __forceinline__ uint32_t s2u(const void* p){
    uint32_t a;
    asm("{ .reg .u64 t; cvta.to.shared.u64 t, %1; cvt.u32.u64 %0, t; }" : "=r"(a) : "l"(p));
    return a;
}
__device__ __forceinline__ void split2h(float v, __half& h, __half& l){
    h = __float2half(v);
    l = __float2half((v - __half2float(h)) * LSCALE);
}

#define LDSM4(r0,r1,r2,r3,a) \
    asm volatile("ldmatrix.sync.aligned.m8n8.x4.shared.b16 {%0,%1,%2,%3}, [%4];" \
        : "=r"(r0),"=r"(r1),"=r"(r2),"=r"(r3) : "r"(a))

#define MMAF32(c,a0,a1,a2,a3,b0,b1) \
    asm volatile("mma.sync.aligned.m16n8k16.row.col.f32.f16.f16.f32 " \
        "{%0,%1,%2,%3},{%4,%5,%6,%7},{%8,%9},{%0,%1,%2,%3};" \
        : "+f"((c)[0]),"+f"((c)[1]),"+f"((c)[2]),"+f"((c)[3]) \
        : "r"(a0),"r"(a1),"r"(a2),"r"(a3),"r"(b0),"r"(b1))

#define MMAF16(c,a0,a1,a2,a3,b0,b1) \
    asm volatile("mma.sync.aligned.m16n8k16.row.col.f16.f16.f16.f16 " \
        "{%0,%1},{%2,%3,%4,%5},{%6,%7},{%0,%1};" \
        : "+r"((c)[0]),"+r"((c)[1]) \
        : "r"(a0),"r"(a1),"r"(a2),"r"(a3),"r"(b0),"r"(b1))

#define CP16(dst,src) \
    asm volatile("cp.async.cg.shared.global [%0], [%1], 16;" :: "r"(dst), "l"(src) : "memory")
#define CP_COMMIT() asm volatile("cp.async.commit_group;" ::: "memory")
#define CP_WAIT1()  asm volatile("cp.async.wait_group 1;" ::: "memory")
#define CP_WAIT0()  asm volatile("cp.async.wait_group 0;" ::: "memory")

// ---------------------------------------------------------------------------
// HMMA GEMM, C[m,n] = sum_k A[m,k]*B[n,k]; operands fp16 planes, K-major.
// PROD=3: hi*hi (f32 acc) + lo*hi + hi*lo (shared f16 acc, lo pre-scaled 2048).
// PROD=1: hi*hi only (half the cp.async traffic / LDSM / MMAs of a product-set).
// EPI 0: +bias -> fp32 C0 and fp16 C1 (row-major)   [Q,K projections]
// EPI 1: +bias -> fp32 C0                           [V projection]
// EPI 2: raw fp32 -> C0 (batched via z,sC)          [cheap scores]
// ---------------------------------------------------------------------------
#define KC 64
#define PITCHB 144
#define TILEB (128*PITCHB)
#define STAGEB (4*TILEB)
#define SMEMSZ (3*STAGEB)

template<int PROD, int EPI>
__global__ __launch_bounds__(256, 1)
void gemm_t(const __half* __restrict__ Ah, const __half* __restrict__ Al,
            const __half* __restrict__ Bh, const __half* __restrict__ Bl,
            const float* __restrict__ bias, void* __restrict__ C0, void* __restrict__ C1,
            int Kg, int ldc, long sA, long sB, long sC)
{
    extern __shared__ __align__(128) char dsm[];
    const int tid = threadIdx.x;
    const int wid = tid >> 5, lane = tid & 31;
    const int warp_m = wid & 3, warp_n = wid >> 2;
    const int m0 = blockIdx.y * 128, n0 = blockIdx.x * 128, z = blockIdx.z;

    const __half* pl[4] = {
        Ah + (size_t)z * sA + (size_t)m0 * Kg,
        Al + (size_t)z * sA + (size_t)m0 * Kg,
        Bh + (size_t)z * sB + (size_t)n0 * Kg,
        Bl + (size_t)z * sB + (size_t)n0 * Kg };

    const uint32_t sb = s2u(dsm);

    auto issue = [&](int c, int s){
        const int kc0 = c * KC;
        const uint32_t st = sb + s * STAGEB;
        if (PROD == 3){
            #pragma unroll
            for (int i = 0; i < 16; i++){
                int idx = tid + i * 256;
                int t = idx >> 10;
                int rem = idx & 1023;
                int r = rem >> 3, q = rem & 7;
                const void* src = pl[t] + (size_t)r * Kg + kc0 + q * 8;
                CP16(st + t * TILEB + r * PITCHB + q * 16, src);
            }
        } else {
            #pragma unroll
            for (int i = 0; i < 8; i++){
                int idx = tid + i * 256;
                int hi = idx >> 10;                  // 0 = Ah tile, 1 = Bh tile
                int rem = idx & 1023;
                int r = rem >> 3, q = rem & 7;
                const void* src = (hi ? pl[2] : pl[0]) + (size_t)r * Kg + kc0 + q * 8;
                CP16(st + (hi ? 2*TILEB : 0) + r * PITCHB + q * 16, src);
            }
        }
        CP_COMMIT();
    };

    const int lrow = lane & 15, lph = lane >> 4;
    uint32_t aA[2], aB[4];
    #pragma unroll
    for (int f = 0; f < 2; f++)
        aA[f] = sb + (warp_m*32 + f*16 + lrow) * PITCHB + lph * 16;
    #pragma unroll
    for (int p = 0; p < 4; p++)
        aB[p] = sb + 2*TILEB + (warp_n*64 + p*16 + lrow) * PITCHB + lph * 16;

    float acc[2][8][4];
    uint32_t accl[2][8][2];
    #pragma unroll
    for (int f = 0; f < 2; f++)
        #pragma unroll
        for (int b = 0; b < 8; b++){
            #pragma unroll
            for (int j = 0; j < 4; j++) acc[f][b][j] = 0.f;
            accl[f][b][0] = 0u; accl[f][b][1] = 0u;
        }

    uint32_t ah[2][2][4], al[2][2][4], bh[2][4][4], bl[2][4][4];

    auto load_frags = [&](int fb, uint32_t so, uint32_t ko){
        #pragma unroll
        for (int f = 0; f < 2; f++){
            LDSM4(ah[fb][f][0],ah[fb][f][1],ah[fb][f][2],ah[fb][f][3], aA[f] + so + ko);
            if (PROD == 3)
                LDSM4(al[fb][f][0],al[fb][f][1],al[fb][f][2],al[fb][f][3], aA[f] + so + ko + TILEB);
        }
        #pragma unroll
        for (int p = 0; p < 4; p++){
            LDSM4(bh[fb][p][0],bh[fb][p][1],bh[fb][p][2],bh[fb][p][3], aB[p] + so + ko);
            if (PROD == 3)
                LDSM4(bl[fb][p][0],bl[fb][p][1],bl[fb][p][2],bl[fb][p][3], aB[p] + so + ko + TILEB);
        }
    };
    auto mma_step = [&](int fb){
        #pragma unroll
        for (int f = 0; f < 2; f++)
            #pragma unroll
            for (int p = 0; p < 4; p++)
                #pragma unroll
                for (int nb = 0; nb < 2; nb++){
                    float*    cc = acc [f][p*2+nb];
                    MMAF32(cc, ah[fb][f][0],ah[fb][f][1],ah[fb][f][2],ah[fb][f][3],
                           bh[fb][p][nb], bh[fb][p][nb+2]);
                    if (PROD == 3){
                        uint32_t* cl = accl[f][p*2+nb];
                        MMAF16(cl, al[fb][f][0],al[fb][f][1],al[fb][f][2],al[fb][f][3],
                               bh[fb][p][nb], bh[fb][p][nb+2]);
                        MMAF16(cl, ah[fb][f][0],ah[fb][f][1],ah[fb][f][2],ah[fb][f][3],
                               bl[fb][p][nb], bl[fb][p][nb+2]);
                    }
                }
    };

    const int NC = Kg / KC;
    issue(0, 0);
    issue(1, 1);

    for (int c = 0; c < NC; c++){
        if (c < NC - 1) CP_WAIT1(); else CP_WAIT0();
        __syncthreads();
        if (c + 2 < NC) issue(c + 2, (c + 2) % 3);

        const uint32_t so = (c % 3) * STAGEB;
        load_frags(0, so, 0);
        #pragma unroll
        for (int ks = 0; ks < 4; ks++){
            if (ks < 3) load_frags((ks + 1) & 1, so, (ks + 1) * 32);
            mma_step(ks & 1);
        }
    }
    __syncthreads();

    // ---- epilogue: merge -> staging smem [128][132] fp32 -> global ----
    float* stg = (float*)dsm;
    const int erow = lane >> 2, ecol2 = (lane & 3) * 2;
    #pragma unroll
    for (int f = 0; f < 2; f++)
        #pragma unroll
        for (int p = 0; p < 4; p++)
            #pragma unroll
            for (int nb = 0; nb < 2; nb++){
                int r  = warp_m*32 + f*16 + erow;
                int cl = warp_n*64 + p*16 + nb*8 + ecol2;
                float* cc = acc[f][p*2+nb];
                float v0 = cc[0], v1 = cc[1], v2 = cc[2], v3 = cc[3];
                if (PROD == 3){
                    uint32_t* lr = accl[f][p*2+nb];
                    float2 w0 = __half22float2(*reinterpret_cast<__half2*>(&lr[0]));
                    float2 w1 = __half22float2(*reinterpret_cast<__half2*>(&lr[1]));
                    v0 += w0.x*LINV; v1 += w0.y*LINV;
                    v2 += w1.x*LINV; v3 += w1.y*LINV;
                }
                *(float2*)&stg[r*132 + cl]     = make_float2(v0, v1);
                *(float2*)&stg[(r+8)*132 + cl] = make_float2(v2, v3);
            }
    __syncthreads();

    #pragma unroll
    for (int i = 0; i < 64; i++){
        int idx = tid + i * 256;
        int j = idx & 127, m = idx >> 7;
        float v = stg[m*132 + j];
        if (EPI == 0){
            v += bias[n0 + j];
            size_t o = (size_t)(m0 + m) * ldc + n0 + j;
            ((float*)C0)[o]  = v;
            ((__half*)C1)[o] = __float2half(v);
        } else if (EPI == 1){
            v += bias[n0 + j];
            ((float*)C0)[(size_t)(m0 + m) * ldc + n0 + j] = v;
        } else {
            ((float*)C0)[(size_t)z * sC + (size_t)(m0 + m) * ldc + n0 + j] = v;
        }
    }
}

// ---------------------------------------------------------------------------
// fp32 -> fp16 hi/lo planes (lo pre-scaled by 2048)
// ---------------------------------------------------------------------------
__global__ __launch_bounds__(256)
void conv_k(const float* __restrict__ in, __half* __restrict__ oh,
            __half* __restrict__ ol, int n4)
{
    int i = blockIdx.x * 256 + threadIdx.x;
    if (i >= n4) return;
    float4 v = ((const float4*)in)[i];
    __half h0,h1,h2,h3,l0,l1,l2,l3;
    split2h(v.x,h0,l0); split2h(v.y,h1,l1); split2h(v.z,h2,l2); split2h(v.w,h3,l3);
    __half2* H = (__half2*)oh;
    __half2* L = (__half2*)ol;
    H[i*2+0] = __halves2half2(h0,h1);
    H[i*2+1] = __halves2half2(h2,h3);
    L[i*2+0] = __halves2half2(l0,l1);
    L[i*2+1] = __halves2half2(l2,l3);
}

// ---------------------------------------------------------------------------
// Fused softmax-select-refine-gather. One CTA (256 thr) per query row.
// Cheap logits select candidates within 21 of row max; candidate logits are
// recomputed exactly from fp32 Q,K; Z = sum of candidate exps (non-candidate
// mass <= 2048*e^-20 ~ 4e-6, dropped); out = sum p_j * V[k_j].
// ---------------------------------------------------------------------------
__global__ __launch_bounds__(256)
void attn_k(const float* __restrict__ Q, const float* __restrict__ K,
            const float* __restrict__ V, float* __restrict__ out)
{
    const int g = blockIdx.x;           // 0..8191 (b*2048 + s)
    const int b = g >> 11;
    const float* srow = g_S + (size_t)g * SS;
    const int tid = threadIdx.x;
    const int lane = tid & 31, w = tid >> 5;

    __shared__ float red[8];
    __shared__ int   s_idx[SS];
    __shared__ float s_p[SS];
    __shared__ int   s_cnt;

    // 1) load logits, row max
    float lv[8];
    float mx = -3.4e38f;
    #pragma unroll
    for (int i = 0; i < 8; i++){ lv[i] = srow[tid + i*256]; mx = fmaxf(mx, lv[i]); }
    #pragma unroll
    for (int o = 16; o; o >>= 1) mx = fmaxf(mx, __shfl_xor_sync(0xffffffffu, mx, o));
    if (lane == 0) red[w] = mx;
    if (tid == 0) s_cnt = 0;
    __syncthreads();
    float m = red[0];
    #pragma unroll
    for (int i = 1; i < 8; i++) m = fmaxf(m, red[i]);

    // 2) select candidates
    const float thr = m - 21.0f;
    #pragma unroll
    for (int i = 0; i < 8; i++){
        if (lv[i] > thr){
            int pos = atomicAdd(&s_cnt, 1);
            s_idx[pos] = tid + i*256;
        }
    }
    __syncthreads();
    const int nc = s_cnt;

    // 3) refine candidate logits in fp32: warp w handles candidates w, w+8, ...
    const float* qr = Q + (size_t)g * DD;
    for (int j = w; j < nc; j += 8){
        const float* kr = K + ((size_t)(b << 11) + s_idx[j]) * DD;
        float a = 0.f;
        #pragma unroll 8
        for (int d = lane; d < DD; d += 32) a += qr[d] * kr[d];
        #pragma unroll
        for (int o = 16; o; o >>= 1) a += __shfl_xor_sync(0xffffffffu, a, o);
        if (lane == 0) s_p[j] = expf(a - m);
    }
    __syncthreads();

    // 4) Z and output
    float Z = 0.f;
    for (int j = 0; j < nc; j++) Z += s_p[j];
    const float invZ = 1.0f / Z;

    float o0 = 0.f, o1 = 0.f, o2 = 0.f, o3 = 0.f;
    for (int j = 0; j < nc; j++){
        const float pj = s_p[j];
        const float* vr = V + ((size_t)(b << 11) + s_idx[j]) * DD;
        o0 += pj * vr[tid];
        o1 += pj * vr[tid + 256];
        o2 += pj * vr[tid + 512];
        o3 += pj * vr[tid + 768];
    }
    float* op = out + (size_t)g * DD;
    op[tid]       = o0 * invZ;
    op[tid + 256] = o1 * invZ;
    op[tid + 512] = o2 * invZ;
    op[tid + 768] = o3 * invZ;
}

// ---------------------------------------------------------------------------
extern "C" void kernel_launch(void* const* d_in, const int* in_sizes, int n_in,
                              void* d_out, int out_size)
{
    const float* x  = (const float*)d_in[0];
    const float* Wq = (const float*)d_in[1];
    const float* bq = (const float*)d_in[2];
    const float* Wk = (const float*)d_in[3];
    const float* bk = (const float*)d_in[4];
    const float* Wv = (const float*)d_in[5];
    const float* bv = (const float*)d_in[6];
    float* out = (float*)d_out;

    __half *xh,*xl,*Wqh,*Wql,*Wkh,*Wkl,*Wvh,*Wvl,*Qh,*Kh;
    float *Qf,*Kf,*Vf,*Sp;
    cudaGetSymbolAddress((void**)&xh,  g_xh);  cudaGetSymbolAddress((void**)&xl,  g_xl);
    cudaGetSymbolAddress((void**)&Wqh, g_Wqh); cudaGetSymbolAddress((void**)&Wql, g_Wql);
    cudaGetSymbolAddress((void**)&Wkh, g_Wkh); cudaGetSymbolAddress((void**)&Wkl, g_Wkl);
    cudaGetSymbolAddress((void**)&Wvh, g_Wvh); cudaGetSymbolAddress((void**)&Wvl, g_Wvl);
    cudaGetSymbolAddress((void**)&Qf,  g_Qf);  cudaGetSymbolAddress((void**)&Kf,  g_Kf);
    cudaGetSymbolAddress((void**)&Vf,  g_Vf);
    cudaGetSymbolAddress((void**)&Qh,  g_Qh);  cudaGetSymbolAddress((void**)&Kh,  g_Kh);
    cudaGetSymbolAddress((void**)&Sp,  g_S);

    cudaFuncSetAttribute((const void*)gemm_t<3,0>, cudaFuncAttributeMaxDynamicSharedMemorySize, SMEMSZ);
    cudaFuncSetAttribute((const void*)gemm_t<3,1>, cudaFuncAttributeMaxDynamicSharedMemorySize, SMEMSZ);
    cudaFuncSetAttribute((const void*)gemm_t<1,2>, cudaFuncAttributeMaxDynamicSharedMemorySize, SMEMSZ);

    // 0) split x and weights into fp16 hi/lo planes
    conv_k<<<(M1*DD/4 + 255)/256, 256>>>(x,  xh,  xl,  M1*DD/4);
    conv_k<<<(DD*DD/4 + 255)/256, 256>>>(Wq, Wqh, Wql, DD*DD/4);
    conv_k<<<(DD*DD/4 + 255)/256, 256>>>(Wk, Wkh, Wkl, DD*DD/4);
    conv_k<<<(DD*DD/4 + 255)/256, 256>>>(Wv, Wvh, Wvl, DD*DD/4);

    // 1) projections (3-product): Q,K -> fp32 + fp16h ; V -> fp32
    dim3 gp(DD/128, M1/128, 1);
    gemm_t<3,0><<<gp, 256, SMEMSZ>>>(xh, xl, Wqh, Wql, bq, Qf, Qh, DD, DD, 0, 0, 0);
    gemm_t<3,0><<<gp, 256, SMEMSZ>>>(xh, xl, Wkh, Wkl, bk, Kf, Kh, DD, DD, 0, 0, 0);
    gemm_t<3,1><<<gp, 256, SMEMSZ>>>(xh, xl, Wvh, Wvl, bv, Vf, nullptr, DD, DD, 0, 0, 0);

    // 2) cheap scores (1-product fp16): logits accurate to ~0.03
    dim3 gs(SS/128, SS/128, BB);
    gemm_t<1,2><<<gs, 256, SMEMSZ>>>(Qh, nullptr, Kh, nullptr, nullptr, Sp, nullptr,
                                     DD, SS, (long)SS*DD, (long)SS*DD, (long)SS*SS);

    // 3) fused softmax-select-refine-gather -> out
    attn_k<<<M1, 256>>>(Qf, Kf, Vf, out);
}

// round 9
// speedup vs baseline: 1.7077x; 1.0881x over previous
#include <cuda_runtime.h>
#include <cuda_fp16.h>
#include <stdint.h>
#include <math.h>

#define BB 4
#define SS 2048
#define DD 1024
#define M1 (BB*SS)

#define LSCALE 2048.0f
#define LINV   (1.0f/2048.0f)

// ---------------------------------------------------------------------------
// Scratch (device globals).
// ---------------------------------------------------------------------------
__device__ __half g_xh [(size_t)M1*DD],  g_xl [(size_t)M1*DD];
__device__ __half g_Wqh[(size_t)DD*DD],  g_Wql[(size_t)DD*DD];
__device__ __half g_Wkh[(size_t)DD*DD],  g_Wkl[(size_t)DD*DD];
__device__ __half g_Wvh[(size_t)DD*DD],  g_Wvl[(size_t)DD*DD];
__device__ float  g_Qf [(size_t)M1*DD];        // fp32 Q (exact refine)
__device__ float  g_Kf [(size_t)M1*DD];        // fp32 K
__device__ float  g_Vf [(size_t)M1*DD];        // fp32 V (gathered)
__device__ __half g_Qh [(size_t)M1*DD];        // fp16 Q (cheap scores)
__device__ __half g_Kh [(size_t)M1*DD];        // fp16 K
__device__ __half g_S  [(size_t)BB*SS*SS];     // approximate logits (fp16)

// ---------------------------------------------------------------------------
__device__ __forceinline__ uint32_t s2u(const void* p){
    uint32_t a;
    asm("{ .reg .u64 t; cvta.to.shared.u64 t, %1; cvt.u32.u64 %0, t; }" : "=r"(a) : "l"(p));
    return a;
}
__device__ __forceinline__ void split2h(float v, __half& h, __half& l){
    h = __float2half(v);
    l = __float2half((v - __half2float(h)) * LSCALE);
}

#define LDSM4(r0,r1,r2,r3,a) \
    asm volatile("ldmatrix.sync.aligned.m8n8.x4.shared.b16 {%0,%1,%2,%3}, [%4];" \
        : "=r"(r0),"=r"(r1),"=r"(r2),"=r"(r3) : "r"(a))

#define MMAF32(c,a0,a1,a2,a3,b0,b1) \
    asm volatile("mma.sync.aligned.m16n8k16.row.col.f32.f16.f16.f32 " \
        "{%0,%1,%2,%3},{%4,%5,%6,%7},{%8,%9},{%0,%1,%2,%3};" \
        : "+f"((c)[0]),"+f"((c)[1]),"+f"((c)[2]),"+f"((c)[3]) \
        : "r"(a0),"r"(a1),"r"(a2),"r"(a3),"r"(b0),"r"(b1))

#define MMAF16(c,a0,a1,a2,a3,b0,b1) \
    asm volatile("mma.sync.aligned.m16n8k16.row.col.f16.f16.f16.f16 " \
        "{%0,%1},{%2,%3,%4,%5},{%6,%7},{%0,%1};" \
        : "+r"((c)[0]),"+r"((c)[1]) \
        : "r"(a0),"r"(a1),"r"(a2),"r"(a3),"r"(b0),"r"(b1))

#define CP16(dst,src) \
    asm volatile("cp.async.cg.shared.global [%0], [%1], 16;" :: "r"(dst), "l"(src) : "memory")
#define CP_COMMIT() asm volatile("cp.async.commit_group;" ::: "memory")
#define CP_WAIT1()  asm volatile("cp.async.wait_group 1;" ::: "memory")
#define CP_WAIT0()  asm volatile("cp.async.wait_group 0;" ::: "memory")

// ---------------------------------------------------------------------------
// HMMA GEMM, C[m,n] = sum_k A[m,k]*B[n,k]; operands fp16 planes, K-major.
// PROD=3: hi*hi (f32) + lo*hi + hi*lo (f16 acc, lo pre-scaled 2048).
// PROD=2: hi*hi (f32) + lo*hi (f16 acc).          [V projection]
// PROD=1: hi*hi only.                             [cheap scores]
// EPI 0: +bias -> fp32 C0 + fp16 C1 (row-major)   [Q,K projections]
// EPI 1: +bias -> fp32 C0                         [V projection]
// EPI 2: fp16 -> C0 (batched via z,sC)            [scores]
// ---------------------------------------------------------------------------
#define KC 64
#define PITCHB 144
#define TILEB (128*PITCHB)
#define STAGEB (4*TILEB)
#define SMEMSZ (3*STAGEB)

template<int PROD, int EPI>
__global__ __launch_bounds__(256, 1)
void gemm_t(const __half* __restrict__ Ah, const __half* __restrict__ Al,
            const __half* __restrict__ Bh, const __half* __restrict__ Bl,
            const float* __restrict__ bias, void* __restrict__ C0, void* __restrict__ C1,
            int Kg, int ldc, long sA, long sB, long sC)
{
    extern __shared__ __align__(128) char dsm[];
    const int tid = threadIdx.x;
    const int wid = tid >> 5, lane = tid & 31;
    const int warp_m = wid & 3, warp_n = wid >> 2;
    const int m0 = blockIdx.y * 128, n0 = blockIdx.x * 128, z = blockIdx.z;

    // tile order: 0=Ah, 1=Al, 2=Bh, 3=Bl  (PROD=2 uses 0,1,2; PROD=1 uses 0,2)
    const __half* pl[4] = {
        Ah + (size_t)z * sA + (size_t)m0 * Kg,
        Al + (size_t)z * sA + (size_t)m0 * Kg,
        Bh + (size_t)z * sB + (size_t)n0 * Kg,
        Bl + (size_t)z * sB + (size_t)n0 * Kg };

    const uint32_t sb = s2u(dsm);

    auto issue = [&](int c, int s){
        const int kc0 = c * KC;
        const uint32_t st = sb + s * STAGEB;
        if (PROD == 3){
            #pragma unroll
            for (int i = 0; i < 16; i++){
                int idx = tid + i * 256;
                int t = idx >> 10;
                int rem = idx & 1023;
                int r = rem >> 3, q = rem & 7;
                CP16(st + t * TILEB + r * PITCHB + q * 16,
                     pl[t] + (size_t)r * Kg + kc0 + q * 8);
            }
        } else if (PROD == 2){
            #pragma unroll
            for (int i = 0; i < 12; i++){
                int idx = tid + i * 256;
                int t = idx >> 10;                 // 0=Ah,1=Al,2=Bh
                int rem = idx & 1023;
                int r = rem >> 3, q = rem & 7;
                CP16(st + t * TILEB + r * PITCHB + q * 16,
                     pl[t] + (size_t)r * Kg + kc0 + q * 8);
            }
        } else {
            #pragma unroll
            for (int i = 0; i < 8; i++){
                int idx = tid + i * 256;
                int hi = idx >> 10;                // 0=Ah, 1=Bh
                int rem = idx & 1023;
                int r = rem >> 3, q = rem & 7;
                CP16(st + (hi ? 2*TILEB : 0) + r * PITCHB + q * 16,
                     pl[hi ? 2 : 0] + (size_t)r * Kg + kc0 + q * 8);
            }
        }
        CP_COMMIT();
    };

    const int lrow = lane & 15, lph = lane >> 4;
    uint32_t aA[2], aB[4];
    #pragma unroll
    for (int f = 0; f < 2; f++)
        aA[f] = sb + (warp_m*32 + f*16 + lrow) * PITCHB + lph * 16;
    #pragma unroll
    for (int p = 0; p < 4; p++)
        aB[p] = sb + 2*TILEB + (warp_n*64 + p*16 + lrow) * PITCHB + lph * 16;

    float acc[2][8][4];
    uint32_t accl[2][8][2];
    #pragma unroll
    for (int f = 0; f < 2; f++)
        #pragma unroll
        for (int b = 0; b < 8; b++){
            #pragma unroll
            for (int j = 0; j < 4; j++) acc[f][b][j] = 0.f;
            accl[f][b][0] = 0u; accl[f][b][1] = 0u;
        }

    uint32_t ah[2][2][4], al[2][2][4], bh[2][4][4], bl[2][4][4];

    auto load_frags = [&](int fb, uint32_t so, uint32_t ko){
        #pragma unroll
        for (int f = 0; f < 2; f++){
            LDSM4(ah[fb][f][0],ah[fb][f][1],ah[fb][f][2],ah[fb][f][3], aA[f] + so + ko);
            if (PROD >= 2)
                LDSM4(al[fb][f][0],al[fb][f][1],al[fb][f][2],al[fb][f][3], aA[f] + so + ko + TILEB);
        }
        #pragma unroll
        for (int p = 0; p < 4; p++){
            LDSM4(bh[fb][p][0],bh[fb][p][1],bh[fb][p][2],bh[fb][p][3], aB[p] + so + ko);
            if (PROD == 3)
                LDSM4(bl[fb][p][0],bl[fb][p][1],bl[fb][p][2],bl[fb][p][3], aB[p] + so + ko + TILEB);
        }
    };
    auto mma_step = [&](int fb){
        #pragma unroll
        for (int f = 0; f < 2; f++)
            #pragma unroll
            for (int p = 0; p < 4; p++)
                #pragma unroll
                for (int nb = 0; nb < 2; nb++){
                    float* cc = acc[f][p*2+nb];
                    MMAF32(cc, ah[fb][f][0],ah[fb][f][1],ah[fb][f][2],ah[fb][f][3],
                           bh[fb][p][nb], bh[fb][p][nb+2]);
                    if (PROD >= 2){
                        uint32_t* cl = accl[f][p*2+nb];
                        MMAF16(cl, al[fb][f][0],al[fb][f][1],al[fb][f][2],al[fb][f][3],
                               bh[fb][p][nb], bh[fb][p][nb+2]);
                        if (PROD == 3)
                            MMAF16(cl, ah[fb][f][0],ah[fb][f][1],ah[fb][f][2],ah[fb][f][3],
                                   bl[fb][p][nb], bl[fb][p][nb+2]);
                    }
                }
    };

    const int NC = Kg / KC;
    issue(0, 0);
    issue(1, 1);

    for (int c = 0; c < NC; c++){
        if (c < NC - 1) CP_WAIT1(); else CP_WAIT0();
        __syncthreads();
        if (c + 2 < NC) issue(c + 2, (c + 2) % 3);

        const uint32_t so = (c % 3) * STAGEB;
        load_frags(0, so, 0);
        #pragma unroll
        for (int ks = 0; ks < 4; ks++){
            if (ks < 3) load_frags((ks + 1) & 1, so, (ks + 1) * 32);
            mma_step(ks & 1);
        }
    }
    __syncthreads();

    // ---- epilogue: merge -> staging smem [128][132] fp32 -> global ----
    float* stg = (float*)dsm;
    const int erow = lane >> 2, ecol2 = (lane & 3) * 2;
    #pragma unroll
    for (int f = 0; f < 2; f++)
        #pragma unroll
        for (int p = 0; p < 4; p++)
            #pragma unroll
            for (int nb = 0; nb < 2; nb++){
                int r  = warp_m*32 + f*16 + erow;
                int cl = warp_n*64 + p*16 + nb*8 + ecol2;
                float* cc = acc[f][p*2+nb];
                float v0 = cc[0], v1 = cc[1], v2 = cc[2], v3 = cc[3];
                if (PROD >= 2){
                    uint32_t* lr = accl[f][p*2+nb];
                    float2 w0 = __half22float2(*reinterpret_cast<__half2*>(&lr[0]));
                    float2 w1 = __half22float2(*reinterpret_cast<__half2*>(&lr[1]));
                    v0 += w0.x*LINV; v1 += w0.y*LINV;
                    v2 += w1.x*LINV; v3 += w1.y*LINV;
                }
                *(float2*)&stg[r*132 + cl]     = make_float2(v0, v1);
                *(float2*)&stg[(r+8)*132 + cl] = make_float2(v2, v3);
            }
    __syncthreads();

    if (EPI == 2){
        #pragma unroll
        for (int i = 0; i < 32; i++){
            int idx = tid + i * 256;
            int j2 = idx & 63, m = idx >> 6;
            float v0 = stg[m*132 + 2*j2], v1 = stg[m*132 + 2*j2 + 1];
            ((__half2*)C0)[((size_t)z * sC + (size_t)(m0 + m) * ldc + n0) / 2 + j2] =
                __floats2half2_rn(v0, v1);
        }
    } else {
        #pragma unroll
        for (int i = 0; i < 64; i++){
            int idx = tid + i * 256;
            int j = idx & 127, m = idx >> 7;
            float v = stg[m*132 + j] + bias[n0 + j];
            size_t o = (size_t)(m0 + m) * ldc + n0 + j;
            ((float*)C0)[o] = v;
            if (EPI == 0) ((__half*)C1)[o] = __float2half(v);
        }
    }
}

// ---------------------------------------------------------------------------
// fp32 -> fp16 hi/lo planes (lo pre-scaled by 2048)
// ---------------------------------------------------------------------------
__global__ __launch_bounds__(256)
void conv_k(const float* __restrict__ in, __half* __restrict__ oh,
            __half* __restrict__ ol, int n4)
{
    int i = blockIdx.x * 256 + threadIdx.x;
    if (i >= n4) return;
    float4 v = ((const float4*)in)[i];
    __half h0,h1,h2,h3,l0,l1,l2,l3;
    split2h(v.x,h0,l0); split2h(v.y,h1,l1); split2h(v.z,h2,l2); split2h(v.w,h3,l3);
    __half2* H = (__half2*)oh;
    __half2* L = (__half2*)ol;
    H[i*2+0] = __halves2half2(h0,h1);
    H[i*2+1] = __halves2half2(h2,h3);
    L[i*2+0] = __halves2half2(l0,l1);
    L[i*2+1] = __halves2half2(l2,l3);
}

// ---------------------------------------------------------------------------
// Fused softmax-select-refine-gather. One CTA (256 thr) per query row.
// ---------------------------------------------------------------------------
__global__ __launch_bounds__(256)
void attn_k(const float* __restrict__ Q, const float* __restrict__ K,
            const float* __restrict__ V, float* __restrict__ out)
{
    const int g = blockIdx.x;           // b*2048 + s
    const int b = g >> 11;
    const __half2* srow = (const __half2*)(g_S + (size_t)g * SS);
    const int tid = threadIdx.x;
    const int lane = tid & 31, w = tid >> 5;

    __shared__ float red[8];
    __shared__ int   s_idx[SS];
    __shared__ float s_p[SS];
    __shared__ int   s_cnt;

    // 1) load logits (fp16), row max
    float lv[8];
    float mx = -3.4e38f;
    #pragma unroll
    for (int i = 0; i < 4; i++){
        float2 v2 = __half22float2(srow[tid + i*256]);
        lv[2*i] = v2.x; lv[2*i+1] = v2.y;
        mx = fmaxf(mx, fmaxf(v2.x, v2.y));
    }
    #pragma unroll
    for (int o = 16; o; o >>= 1) mx = fmaxf(mx, __shfl_xor_sync(0xffffffffu, mx, o));
    if (lane == 0) red[w] = mx;
    if (tid == 0) s_cnt = 0;
    __syncthreads();
    float m = red[0];
    #pragma unroll
    for (int i = 1; i < 8; i++) m = fmaxf(m, red[i]);

    // 2) select candidates within 21 of row max
    const float thr = m - 21.0f;
    #pragma unroll
    for (int i = 0; i < 4; i++){
        if (lv[2*i] > thr){
            int pos = atomicAdd(&s_cnt, 1);
            s_idx[pos] = 2*(tid + i*256);
        }
        if (lv[2*i+1] > thr){
            int pos = atomicAdd(&s_cnt, 1);
            s_idx[pos] = 2*(tid + i*256) + 1;
        }
    }
    __syncthreads();
    const int nc = s_cnt;

    // 3) refine candidate logits exactly in fp32
    const float* qr = Q + (size_t)g * DD;
    for (int j = w; j < nc; j += 8){
        const float* kr = K + ((size_t)(b << 11) + s_idx[j]) * DD;
        float a = 0.f;
        #pragma unroll 8
        for (int d = lane; d < DD; d += 32) a += qr[d] * kr[d];
        #pragma unroll
        for (int o = 16; o; o >>= 1) a += __shfl_xor_sync(0xffffffffu, a, o);
        if (lane == 0) s_p[j] = expf(a - m);
    }
    __syncthreads();

    // 4) Z and gathered output (float4 per thread)
    float Z = 0.f;
    for (int j = 0; j < nc; j++) Z += s_p[j];
    const float invZ = 1.0f / Z;

    float4 o4 = make_float4(0.f, 0.f, 0.f, 0.f);
    for (int j = 0; j < nc; j++){
        const float pj = s_p[j];
        float4 vv = ((const float4*)(V + ((size_t)(b << 11) + s_idx[j]) * DD))[tid];
        o4.x += pj * vv.x; o4.y += pj * vv.y;
        o4.z += pj * vv.z; o4.w += pj * vv.w;
    }
    o4.x *= invZ; o4.y *= invZ; o4.z *= invZ; o4.w *= invZ;
    ((float4*)(out + (size_t)g * DD))[tid] = o4;
}

// ---------------------------------------------------------------------------
extern "C" void kernel_launch(void* const* d_in, const int* in_sizes, int n_in,
                              void* d_out, int out_size)
{
    const float* x  = (const float*)d_in[0];
    const float* Wq = (const float*)d_in[1];
    const float* bq = (const float*)d_in[2];
    const float* Wk = (const float*)d_in[3];
    const float* bk = (const float*)d_in[4];
    const float* Wv = (const float*)d_in[5];
    const float* bv = (const float*)d_in[6];
    float* out = (float*)d_out;

    __half *xh,*xl,*Wqh,*Wql,*Wkh,*Wkl,*Wvh,*Wvl,*Qh,*Kh,*Sp;
    float *Qf,*Kf,*Vf;
    cudaGetSymbolAddress((void**)&xh,  g_xh);  cudaGetSymbolAddress((void**)&xl,  g_xl);
    cudaGetSymbolAddress((void**)&Wqh, g_Wqh); cudaGetSymbolAddress((void**)&Wql, g_Wql);
    cudaGetSymbolAddress((void**)&Wkh, g_Wkh); cudaGetSymbolAddress((void**)&Wkl, g_Wkl);
    cudaGetSymbolAddress((void**)&Wvh, g_Wvh); cudaGetSymbolAddress((void**)&Wvl, g_Wvl);
    cudaGetSymbolAddress((void**)&Qf,  g_Qf);  cudaGetSymbolAddress((void**)&Kf,  g_Kf);
    cudaGetSymbolAddress((void**)&Vf,  g_Vf);
    cudaGetSymbolAddress((void**)&Qh,  g_Qh);  cudaGetSymbolAddress((void**)&Kh,  g_Kh);
    cudaGetSymbolAddress((void**)&Sp,  g_S);

    cudaFuncSetAttribute((const void*)gemm_t<3,0>, cudaFuncAttributeMaxDynamicSharedMemorySize, SMEMSZ);
    cudaFuncSetAttribute((const void*)gemm_t<2,1>, cudaFuncAttributeMaxDynamicSharedMemorySize, SMEMSZ);
    cudaFuncSetAttribute((const void*)gemm_t<1,2>, cudaFuncAttributeMaxDynamicSharedMemorySize, SMEMSZ);

    // 0) split x and weights into fp16 hi/lo planes
    conv_k<<<(M1*DD/4 + 255)/256, 256>>>(x,  xh,  xl,  M1*DD/4);
    conv_k<<<(DD*DD/4 + 255)/256, 256>>>(Wq, Wqh, Wql, DD*DD/4);
    conv_k<<<(DD*DD/4 + 255)/256, 256>>>(Wk, Wkh, Wkl, DD*DD/4);
    conv_k<<<(DD*DD/4 + 255)/256, 256>>>(Wv, Wvh, Wvl, DD*DD/4);

    // 1) projections: Q,K 3-product -> fp32 + fp16h ; V 2-product -> fp32
    dim3 gp(DD/128, M1/128, 1);
    gemm_t<3,0><<<gp, 256, SMEMSZ>>>(xh, xl, Wqh, Wql, bq, Qf, Qh, DD, DD, 0, 0, 0);
    gemm_t<3,0><<<gp, 256, SMEMSZ>>>(xh, xl, Wkh, Wkl, bk, Kf, Kh, DD, DD, 0, 0, 0);
    gemm_t<2,1><<<gp, 256, SMEMSZ>>>(xh, xl, Wvh, Wvl, bv, Vf, nullptr, DD, DD, 0, 0, 0);

    // 2) cheap scores (1-product fp16) -> fp16 logits
    dim3 gs(SS/128, SS/128, BB);
    gemm_t<1,2><<<gs, 256, SMEMSZ>>>(Qh, nullptr, Kh, nullptr, nullptr, Sp, nullptr,
                                     DD, SS, (long)SS*DD, (long)SS*DD, (long)SS*SS);

    // 3) fused softmax-select-refine-gather -> out
    attn_k<<<M1, 256>>>(Qf, Kf, Vf, out);
}

// round 10
// speedup vs baseline: 1.7405x; 1.0192x over previous
#include <cuda_runtime.h>
#include <cuda_fp16.h>
#include <stdint.h>
#include <math.h>

#define BB 4
#define SS 2048
#define DD 1024
#define M1 (BB*SS)

#define LSCALE 2048.0f
#define LINV   (1.0f/2048.0f)

// ---------------------------------------------------------------------------
// Scratch (device globals).
// ---------------------------------------------------------------------------
__device__ __half g_xh [(size_t)M1*DD],  g_xl [(size_t)M1*DD];
__device__ __half g_Wqh[(size_t)DD*DD],  g_Wql[(size_t)DD*DD];
__device__ __half g_Wkh[(size_t)DD*DD],  g_Wkl[(size_t)DD*DD];
__device__ __half g_Wvh[(size_t)DD*DD],  g_Wvl[(size_t)DD*DD];
__device__ float  g_Qf [(size_t)M1*DD];
__device__ float  g_Kf [(size_t)M1*DD];
__device__ float  g_Vf [(size_t)M1*DD];
__device__ __half g_Qh [(size_t)M1*DD];
__device__ __half g_Kh [(size_t)M1*DD];
__device__ __half g_S  [(size_t)BB*SS*SS];

// ---------------------------------------------------------------------------
__device__ __forceinline__ uint32_t s2u(const void* p){
    uint32_t a;
    asm("{ .reg .u64 t; cvta.to.shared.u64 t, %1; cvt.u32.u64 %0, t; }" : "=r"(a) : "l"(p));
    return a;
}
__device__ __forceinline__ void split2h(float v, __half& h, __half& l){
    h = __float2half(v);
    l = __float2half((v - __half2float(h)) * LSCALE);
}

#define LDSM4(r0,r1,r2,r3,a) \
    asm volatile("ldmatrix.sync.aligned.m8n8.x4.shared.b16 {%0,%1,%2,%3}, [%4];" \
        : "=r"(r0),"=r"(r1),"=r"(r2),"=r"(r3) : "r"(a))

#define MMAF32(c,a0,a1,a2,a3,b0,b1) \
    asm volatile("mma.sync.aligned.m16n8k16.row.col.f32.f16.f16.f32 " \
        "{%0,%1,%2,%3},{%4,%5,%6,%7},{%8,%9},{%0,%1,%2,%3};" \
        : "+f"((c)[0]),"+f"((c)[1]),"+f"((c)[2]),"+f"((c)[3]) \
        : "r"(a0),"r"(a1),"r"(a2),"r"(a3),"r"(b0),"r"(b1))

#define MMAF16(c,a0,a1,a2,a3,b0,b1) \
    asm volatile("mma.sync.aligned.m16n8k16.row.col.f16.f16.f16.f16 " \
        "{%0,%1},{%2,%3,%4,%5},{%6,%7},{%0,%1};" \
        : "+r"((c)[0]),"+r"((c)[1]) \
        : "r"(a0),"r"(a1),"r"(a2),"r"(a3),"r"(b0),"r"(b1))

#define CP16(dst,src) \
    asm volatile("cp.async.cg.shared.global [%0], [%1], 16;" :: "r"(dst), "l"(src) : "memory")
#define CP_COMMIT() asm volatile("cp.async.commit_group;" ::: "memory")
#define CP_WAIT1()  asm volatile("cp.async.wait_group 1;" ::: "memory")
#define CP_WAIT0()  asm volatile("cp.async.wait_group 0;" ::: "memory")

#define KC 64
#define PITCHB 144
#define TILEB (128*PITCHB)
#define STAGEB (4*TILEB)
#define SMEMSZ (3*STAGEB)

// ---------------------------------------------------------------------------
// Merged Q/K/V projection GEMM. One launch, blockIdx.z selects output:
//   z=0: Q = x@Wq^T+bq  (3-product) -> fp32 Qf + fp16 Qh
//   z=1: K = x@Wk^T+bk  (3-product) -> fp32 Kf + fp16 Kh
//   z=2: V = x@Wv^T+bv  (2-product) -> fp32 Vf
// CTA 128x128, 256 thr, KC=64, 3-stage cp.async, frag double-buffering.
// ---------------------------------------------------------------------------
__global__ __launch_bounds__(256, 1)
void gemm_qkv(const __half* __restrict__ xh, const __half* __restrict__ xl,
              const __half* __restrict__ Wqh, const __half* __restrict__ Wql,
              const __half* __restrict__ Wkh, const __half* __restrict__ Wkl,
              const __half* __restrict__ Wvh, const __half* __restrict__ Wvl,
              const float* __restrict__ bq, const float* __restrict__ bk,
              const float* __restrict__ bv,
              float* __restrict__ Qf, float* __restrict__ Kf, float* __restrict__ Vf,
              __half* __restrict__ Qh, __half* __restrict__ Kh)
{
    extern __shared__ __align__(128) char dsm[];
    const int tid = threadIdx.x;
    const int wid = tid >> 5, lane = tid & 31;
    const int warp_m = wid & 3, warp_n = wid >> 2;
    const int m0 = blockIdx.y * 128, n0 = blockIdx.x * 128;
    const int z = blockIdx.z;
    const bool p3 = (z != 2);           // 3-product for Q,K; 2 for V

    const __half* Bh_ = (z == 0) ? Wqh : (z == 1) ? Wkh : Wvh;
    const __half* Bl_ = (z == 0) ? Wql : (z == 1) ? Wkl : Wvl;
    const float*  bias = (z == 0) ? bq : (z == 1) ? bk : bv;
    float* Cf  = (z == 0) ? Qf : (z == 1) ? Kf : Vf;
    __half* Ch = (z == 0) ? Qh : (z == 1) ? Kh : nullptr;

    const __half* pl[4] = {
        xh + (size_t)m0 * DD, xl + (size_t)m0 * DD,
        Bh_ + (size_t)n0 * DD, Bl_ + (size_t)n0 * DD };

    const uint32_t sb = s2u(dsm);

    auto issue = [&](int c, int s){
        const int kc0 = c * KC;
        const uint32_t st = sb + s * STAGEB;
        #pragma unroll
        for (int i = 0; i < 16; i++){
            int idx = tid + i * 256;
            int t = idx >> 10;
            if (t == 3 && !p3) continue;     // skip Bl tile for V
            int rem = idx & 1023;
            int r = rem >> 3, q = rem & 7;
            CP16(st + t * TILEB + r * PITCHB + q * 16,
                 pl[t] + (size_t)r * DD + kc0 + q * 8);
        }
        CP_COMMIT();
    };

    const int lrow = lane & 15, lph = lane >> 4;
    uint32_t aA[2], aB[4];
    #pragma unroll
    for (int f = 0; f < 2; f++)
        aA[f] = sb + (warp_m*32 + f*16 + lrow) * PITCHB + lph * 16;
    #pragma unroll
    for (int p = 0; p < 4; p++)
        aB[p] = sb + 2*TILEB + (warp_n*64 + p*16 + lrow) * PITCHB + lph * 16;

    float acc[2][8][4];
    uint32_t accl[2][8][2];
    #pragma unroll
    for (int f = 0; f < 2; f++)
        #pragma unroll
        for (int b = 0; b < 8; b++){
            #pragma unroll
            for (int j = 0; j < 4; j++) acc[f][b][j] = 0.f;
            accl[f][b][0] = 0u; accl[f][b][1] = 0u;
        }

    uint32_t ah[2][2][4], al[2][2][4], bh[2][4][4], bl[2][4][4];

    auto load_frags = [&](int fb, uint32_t so, uint32_t ko){
        #pragma unroll
        for (int f = 0; f < 2; f++){
            LDSM4(ah[fb][f][0],ah[fb][f][1],ah[fb][f][2],ah[fb][f][3], aA[f] + so + ko);
            LDSM4(al[fb][f][0],al[fb][f][1],al[fb][f][2],al[fb][f][3], aA[f] + so + ko + TILEB);
        }
        #pragma unroll
        for (int p = 0; p < 4; p++){
            LDSM4(bh[fb][p][0],bh[fb][p][1],bh[fb][p][2],bh[fb][p][3], aB[p] + so + ko);
            if (p3)
                LDSM4(bl[fb][p][0],bl[fb][p][1],bl[fb][p][2],bl[fb][p][3], aB[p] + so + ko + TILEB);
        }
    };
    auto mma_step = [&](int fb){
        #pragma unroll
        for (int f = 0; f < 2; f++)
            #pragma unroll
            for (int p = 0; p < 4; p++)
                #pragma unroll
                for (int nb = 0; nb < 2; nb++){
                    float* cc = acc[f][p*2+nb];
                    uint32_t* cl = accl[f][p*2+nb];
                    MMAF32(cc, ah[fb][f][0],ah[fb][f][1],ah[fb][f][2],ah[fb][f][3],
                           bh[fb][p][nb], bh[fb][p][nb+2]);
                    MMAF16(cl, al[fb][f][0],al[fb][f][1],al[fb][f][2],al[fb][f][3],
                           bh[fb][p][nb], bh[fb][p][nb+2]);
                    if (p3)
                        MMAF16(cl, ah[fb][f][0],ah[fb][f][1],ah[fb][f][2],ah[fb][f][3],
                               bl[fb][p][nb], bl[fb][p][nb+2]);
                }
    };

    const int NC = DD / KC;
    issue(0, 0);
    issue(1, 1);

    for (int c = 0; c < NC; c++){
        if (c < NC - 1) CP_WAIT1(); else CP_WAIT0();
        __syncthreads();
        if (c + 2 < NC) issue(c + 2, (c + 2) % 3);

        const uint32_t so = (c % 3) * STAGEB;
        load_frags(0, so, 0);
        #pragma unroll
        for (int ks = 0; ks < 4; ks++){
            if (ks < 3) load_frags((ks + 1) & 1, so, (ks + 1) * 32);
            mma_step(ks & 1);
        }
    }
    __syncthreads();

    // ---- epilogue ----
    float* stg = (float*)dsm;
    const int erow = lane >> 2, ecol2 = (lane & 3) * 2;
    #pragma unroll
    for (int f = 0; f < 2; f++)
        #pragma unroll
        for (int p = 0; p < 4; p++)
            #pragma unroll
            for (int nb = 0; nb < 2; nb++){
                int r  = warp_m*32 + f*16 + erow;
                int cl = warp_n*64 + p*16 + nb*8 + ecol2;
                float* cc = acc[f][p*2+nb];
                uint32_t* lr = accl[f][p*2+nb];
                float2 w0 = __half22float2(*reinterpret_cast<__half2*>(&lr[0]));
                float2 w1 = __half22float2(*reinterpret_cast<__half2*>(&lr[1]));
                *(float2*)&stg[r*132 + cl] =
                    make_float2(cc[0] + w0.x*LINV, cc[1] + w0.y*LINV);
                *(float2*)&stg[(r+8)*132 + cl] =
                    make_float2(cc[2] + w1.x*LINV, cc[3] + w1.y*LINV);
            }
    __syncthreads();

    #pragma unroll
    for (int i = 0; i < 64; i++){
        int idx = tid + i * 256;
        int j = idx & 127, m = idx >> 7;
        float v = stg[m*132 + j] + bias[n0 + j];
        size_t o = (size_t)(m0 + m) * DD + n0 + j;
        Cf[o] = v;
        if (p3) Ch[o] = __float2half(v);
    }
}

// ---------------------------------------------------------------------------
// Cheap scores GEMM: S[z][m][n] = sum_k Qh[m,k]*Kh[n,k], fp16 out.
// ---------------------------------------------------------------------------
__global__ __launch_bounds__(256, 1)
void gemm_s(const __half* __restrict__ Qh, const __half* __restrict__ Kh,
            __half* __restrict__ Sout)
{
    extern __shared__ __align__(128) char dsm[];
    const int tid = threadIdx.x;
    const int wid = tid >> 5, lane = tid & 31;
    const int warp_m = wid & 3, warp_n = wid >> 2;
    const int m0 = blockIdx.y * 128, n0 = blockIdx.x * 128, z = blockIdx.z;

    const __half* pA = Qh + (size_t)z * SS * DD + (size_t)m0 * DD;
    const __half* pB = Kh + (size_t)z * SS * DD + (size_t)n0 * DD;

    const uint32_t sb = s2u(dsm);

    auto issue = [&](int c, int s){
        const int kc0 = c * KC;
        const uint32_t st = sb + s * STAGEB;
        #pragma unroll
        for (int i = 0; i < 8; i++){
            int idx = tid + i * 256;
            int hi = idx >> 10;
            int rem = idx & 1023;
            int r = rem >> 3, q = rem & 7;
            CP16(st + (hi ? 2*TILEB : 0) + r * PITCHB + q * 16,
                 (hi ? pB : pA) + (size_t)r * DD + kc0 + q * 8);
        }
        CP_COMMIT();
    };

    const int lrow = lane & 15, lph = lane >> 4;
    uint32_t aA[2], aB[4];
    #pragma unroll
    for (int f = 0; f < 2; f++)
        aA[f] = sb + (warp_m*32 + f*16 + lrow) * PITCHB + lph * 16;
    #pragma unroll
    for (int p = 0; p < 4; p++)
        aB[p] = sb + 2*TILEB + (warp_n*64 + p*16 + lrow) * PITCHB + lph * 16;

    float acc[2][8][4];
    #pragma unroll
    for (int f = 0; f < 2; f++)
        #pragma unroll
        for (int b = 0; b < 8; b++)
            #pragma unroll
            for (int j = 0; j < 4; j++) acc[f][b][j] = 0.f;

    uint32_t ah[2][2][4], bh[2][4][4];
    auto load_frags = [&](int fb, uint32_t so, uint32_t ko){
        #pragma unroll
        for (int f = 0; f < 2; f++)
            LDSM4(ah[fb][f][0],ah[fb][f][1],ah[fb][f][2],ah[fb][f][3], aA[f] + so + ko);
        #pragma unroll
        for (int p = 0; p < 4; p++)
            LDSM4(bh[fb][p][0],bh[fb][p][1],bh[fb][p][2],bh[fb][p][3], aB[p] + so + ko);
    };
    auto mma_step = [&](int fb){
        #pragma unroll
        for (int f = 0; f < 2; f++)
            #pragma unroll
            for (int p = 0; p < 4; p++)
                #pragma unroll
                for (int nb = 0; nb < 2; nb++)
                    MMAF32(acc[f][p*2+nb], ah[fb][f][0],ah[fb][f][1],ah[fb][f][2],ah[fb][f][3],
                           bh[fb][p][nb], bh[fb][p][nb+2]);
    };

    const int NC = DD / KC;
    issue(0, 0);
    issue(1, 1);
    for (int c = 0; c < NC; c++){
        if (c < NC - 1) CP_WAIT1(); else CP_WAIT0();
        __syncthreads();
        if (c + 2 < NC) issue(c + 2, (c + 2) % 3);
        const uint32_t so = (c % 3) * STAGEB;
        load_frags(0, so, 0);
        #pragma unroll
        for (int ks = 0; ks < 4; ks++){
            if (ks < 3) load_frags((ks + 1) & 1, so, (ks + 1) * 32);
            mma_step(ks & 1);
        }
    }
    __syncthreads();

    float* stg = (float*)dsm;
    const int erow = lane >> 2, ecol2 = (lane & 3) * 2;
    #pragma unroll
    for (int f = 0; f < 2; f++)
        #pragma unroll
        for (int p = 0; p < 4; p++)
            #pragma unroll
            for (int nb = 0; nb < 2; nb++){
                int r  = warp_m*32 + f*16 + erow;
                int cl = warp_n*64 + p*16 + nb*8 + ecol2;
                float* cc = acc[f][p*2+nb];
                *(float2*)&stg[r*132 + cl]     = make_float2(cc[0], cc[1]);
                *(float2*)&stg[(r+8)*132 + cl] = make_float2(cc[2], cc[3]);
            }
    __syncthreads();

    #pragma unroll
    for (int i = 0; i < 32; i++){
        int idx = tid + i * 256;
        int j2 = idx & 63, m = idx >> 6;
        float v0 = stg[m*132 + 2*j2], v1 = stg[m*132 + 2*j2 + 1];
        ((__half2*)Sout)[((size_t)z * SS * SS + (size_t)(m0 + m) * SS + n0) / 2 + j2] =
            __floats2half2_rn(v0, v1);
    }
}

// ---------------------------------------------------------------------------
// Conversions: x (z=0 sized M1*DD) handled by conv_x; weights merged in conv_w.
// ---------------------------------------------------------------------------
__global__ __launch_bounds__(256)
void conv_x(const float* __restrict__ in, __half* __restrict__ oh,
            __half* __restrict__ ol)
{
    int i = blockIdx.x * 256 + threadIdx.x;
    float4 v = ((const float4*)in)[i];
    __half h0,h1,h2,h3,l0,l1,l2,l3;
    split2h(v.x,h0,l0); split2h(v.y,h1,l1); split2h(v.z,h2,l2); split2h(v.w,h3,l3);
    __half2* H = (__half2*)oh;  __half2* L = (__half2*)ol;
    H[i*2+0] = __halves2half2(h0,h1);  H[i*2+1] = __halves2half2(h2,h3);
    L[i*2+0] = __halves2half2(l0,l1);  L[i*2+1] = __halves2half2(l2,l3);
}

__global__ __launch_bounds__(256)
void conv_w(const float* __restrict__ Wq, const float* __restrict__ Wk,
            const float* __restrict__ Wv)
{
    int i = blockIdx.x * 256 + threadIdx.x;
    int z = blockIdx.y;
    const float* in = (z == 0) ? Wq : (z == 1) ? Wk : Wv;
    __half* oh = (z == 0) ? g_Wqh : (z == 1) ? g_Wkh : g_Wvh;
    __half* ol = (z == 0) ? g_Wql : (z == 1) ? g_Wkl : g_Wvl;
    float4 v = ((const float4*)in)[i];
    __half h0,h1,h2,h3,l0,l1,l2,l3;
    split2h(v.x,h0,l0); split2h(v.y,h1,l1); split2h(v.z,h2,l2); split2h(v.w,h3,l3);
    __half2* H = (__half2*)oh;  __half2* L = (__half2*)ol;
    H[i*2+0] = __halves2half2(h0,h1);  H[i*2+1] = __halves2half2(h2,h3);
    L[i*2+0] = __halves2half2(l0,l1);  L[i*2+1] = __halves2half2(l2,l3);
}

// ---------------------------------------------------------------------------
// Fused softmax-select-refine-gather. One CTA (256 thr) per query row.
// ---------------------------------------------------------------------------
__global__ __launch_bounds__(256)
void attn_k(const float* __restrict__ Q, const float* __restrict__ K,
            const float* __restrict__ V, float* __restrict__ out)
{
    const int g = blockIdx.x;
    const int b = g >> 11;
    const __half2* srow = (const __half2*)(g_S + (size_t)g * SS);
    const int tid = threadIdx.x;
    const int lane = tid & 31, w = tid >> 5;

    __shared__ float red[8];
    __shared__ int   s_idx[SS];
    __shared__ float s_p[SS];
    __shared__ int   s_cnt;

    float lv[8];
    float mx = -3.4e38f;
    #pragma unroll
    for (int i = 0; i < 4; i++){
        float2 v2 = __half22float2(srow[tid + i*256]);
        lv[2*i] = v2.x; lv[2*i+1] = v2.y;
        mx = fmaxf(mx, fmaxf(v2.x, v2.y));
    }
    #pragma unroll
    for (int o = 16; o; o >>= 1) mx = fmaxf(mx, __shfl_xor_sync(0xffffffffu, mx, o));
    if (lane == 0) red[w] = mx;
    if (tid == 0) s_cnt = 0;
    __syncthreads();
    float m = red[0];
    #pragma unroll
    for (int i = 1; i < 8; i++) m = fmaxf(m, red[i]);

    const float thr = m - 18.0f;
    #pragma unroll
    for (int i = 0; i < 4; i++){
        if (lv[2*i] > thr){
            int pos = atomicAdd(&s_cnt, 1);
            s_idx[pos] = 2*(tid + i*256);
        }
        if (lv[2*i+1] > thr){
            int pos = atomicAdd(&s_cnt, 1);
            s_idx[pos] = 2*(tid + i*256) + 1;
        }
    }
    __syncthreads();
    const int nc = s_cnt;

    const float* qr = Q + (size_t)g * DD;
    for (int j = w; j < nc; j += 8){
        const float* kr = K + ((size_t)(b << 11) + s_idx[j]) * DD;
        float a = 0.f;
        #pragma unroll 8
        for (int d = lane; d < DD; d += 32) a += qr[d] * kr[d];
        #pragma unroll
        for (int o = 16; o; o >>= 1) a += __shfl_xor_sync(0xffffffffu, a, o);
        if (lane == 0) s_p[j] = expf(a - m);
    }
    __syncthreads();

    float Z = 0.f;
    for (int j = 0; j < nc; j++) Z += s_p[j];
    const float invZ = 1.0f / Z;

    float4 o4 = make_float4(0.f, 0.f, 0.f, 0.f);
    for (int j = 0; j < nc; j++){
        const float pj = s_p[j];
        float4 vv = ((const float4*)(V + ((size_t)(b << 11) + s_idx[j]) * DD))[tid];
        o4.x += pj * vv.x; o4.y += pj * vv.y;
        o4.z += pj * vv.z; o4.w += pj * vv.w;
    }
    o4.x *= invZ; o4.y *= invZ; o4.z *= invZ; o4.w *= invZ;
    ((float4*)(out + (size_t)g * DD))[tid] = o4;
}

// ---------------------------------------------------------------------------
extern "C" void kernel_launch(void* const* d_in, const int* in_sizes, int n_in,
                              void* d_out, int out_size)
{
    const float* x  = (const float*)d_in[0];
    const float* Wq = (const float*)d_in[1];
    const float* bq = (const float*)d_in[2];
    const float* Wk = (const float*)d_in[3];
    const float* bk = (const float*)d_in[4];
    const float* Wv = (const float*)d_in[5];
    const float* bv = (const float*)d_in[6];
    float* out = (float*)d_out;

    __half *xh,*xl,*Wqh,*Wql,*Wkh,*Wkl,*Wvh,*Wvl,*Qh,*Kh,*Sp;
    float *Qf,*Kf,*Vf;
    cudaGetSymbolAddress((void**)&xh,  g_xh);  cudaGetSymbolAddress((void**)&xl,  g_xl);
    cudaGetSymbolAddress((void**)&Wqh, g_Wqh); cudaGetSymbolAddress((void**)&Wql, g_Wql);
    cudaGetSymbolAddress((void**)&Wkh, g_Wkh); cudaGetSymbolAddress((void**)&Wkl, g_Wkl);
    cudaGetSymbolAddress((void**)&Wvh, g_Wvh); cudaGetSymbolAddress((void**)&Wvl, g_Wvl);
    cudaGetSymbolAddress((void**)&Qf,  g_Qf);  cudaGetSymbolAddress((void**)&Kf,  g_Kf);
    cudaGetSymbolAddress((void**)&Vf,  g_Vf);
    cudaGetSymbolAddress((void**)&Qh,  g_Qh);  cudaGetSymbolAddress((void**)&Kh,  g_Kh);
    cudaGetSymbolAddress((void**)&Sp,  g_S);

    cudaFuncSetAttribute(gemm_qkv, cudaFuncAttributeMaxDynamicSharedMemorySize, SMEMSZ);
    cudaFuncSetAttribute(gemm_s,   cudaFuncAttributeMaxDynamicSharedMemorySize, SMEMSZ);

    // 0) splits: x, then all three weights in one launch
    conv_x<<<M1*DD/4/256, 256>>>(x, xh, xl);
    conv_w<<<dim3(DD*DD/4/256, 3), 256>>>(Wq, Wk, Wv);

    // 1) merged projections (z: 0=Q, 1=K, 2=V)
    dim3 gp(DD/128, M1/128, 3);
    gemm_qkv<<<gp, 256, SMEMSZ>>>(xh, xl, Wqh, Wql, Wkh, Wkl, Wvh, Wvl,
                                  bq, bk, bv, Qf, Kf, Vf, Qh, Kh);

    // 2) cheap scores
    dim3 gs(SS/128, SS/128, BB);
    gemm_s<<<gs, 256, SMEMSZ>>>(Qh, Kh, Sp);

    // 3) fused softmax-select-refine-gather
    attn_k<<<M1, 256>>>(Qf, Kf, Vf, out);
}

// round 11
// speedup vs baseline: 1.9054x; 1.0947x over previous
#include <cuda_runtime.h>
#include <cuda_fp16.h>
#include <stdint.h>
#include <math.h>

#define BB 4
#define SS 2048
#define DD 1024
#define M1 (BB*SS)

#define LSCALE 2048.0f
#define LINV   (1.0f/2048.0f)

// ---------------------------------------------------------------------------
// Scratch (device globals).
// ---------------------------------------------------------------------------
__device__ __half g_xh [(size_t)M1*DD],  g_xl [(size_t)M1*DD];
__device__ __half g_Wqh[(size_t)DD*DD],  g_Wql[(size_t)DD*DD];
__device__ __half g_Wkh[(size_t)DD*DD],  g_Wkl[(size_t)DD*DD];
__device__ __half g_Wvh[(size_t)DD*DD],  g_Wvl[(size_t)DD*DD];
__device__ float  g_Qf [(size_t)M1*DD];
__device__ float  g_Kf [(size_t)M1*DD];
__device__ float  g_Vf [(size_t)M1*DD];
__device__ __half g_Qh [(size_t)M1*DD];
__device__ __half g_Kh [(size_t)M1*DD];
__device__ __half g_S  [(size_t)BB*SS*SS];

// ---------------------------------------------------------------------------
__device__ __forceinline__ uint32_t s2u(const void* p){
    uint32_t a;
    asm("{ .reg .u64 t; cvta.to.shared.u64 t, %1; cvt.u32.u64 %0, t; }" : "=r"(a) : "l"(p));
    return a;
}
__device__ __forceinline__ void split2h(float v, __half& h, __half& l){
    h = __float2half(v);
    l = __float2half((v - __half2float(h)) * LSCALE);
}

#define LDSM4(r0,r1,r2,r3,a) \
    asm volatile("ldmatrix.sync.aligned.m8n8.x4.shared.b16 {%0,%1,%2,%3}, [%4];" \
        : "=r"(r0),"=r"(r1),"=r"(r2),"=r"(r3) : "r"(a))

#define MMAF32(c,a0,a1,a2,a3,b0,b1) \
    asm volatile("mma.sync.aligned.m16n8k16.row.col.f32.f16.f16.f32 " \
        "{%0,%1,%2,%3},{%4,%5,%6,%7},{%8,%9},{%0,%1,%2,%3};" \
        : "+f"((c)[0]),"+f"((c)[1]),"+f"((c)[2]),"+f"((c)[3]) \
        : "r"(a0),"r"(a1),"r"(a2),"r"(a3),"r"(b0),"r"(b1))

#define MMAF16(c,a0,a1,a2,a3,b0,b1) \
    asm volatile("mma.sync.aligned.m16n8k16.row.col.f16.f16.f16.f16 " \
        "{%0,%1},{%2,%3,%4,%5},{%6,%7},{%0,%1};" \
        : "+r"((c)[0]),"+r"((c)[1]) \
        : "r"(a0),"r"(a1),"r"(a2),"r"(a3),"r"(b0),"r"(b1))

#define CP16(dst,src) \
    asm volatile("cp.async.cg.shared.global [%0], [%1], 16;" :: "r"(dst), "l"(src) : "memory")
#define CP_COMMIT() asm volatile("cp.async.commit_group;" ::: "memory")
#define CP_WAIT1()  asm volatile("cp.async.wait_group 1;" ::: "memory")
#define CP_WAIT0()  asm volatile("cp.async.wait_group 0;" ::: "memory")

#define PITCHB 144      // 128B data + 16B pad per row (KC=64 halfs)

// ===========================================================================
// gemm_qkv: CTA tile 128x64, 8 warps (4m x 2n), warp tile 32x32, KC=64,
// 2-stage cp.async, single-buffered frags. smem/CTA = 108 KB -> 2 CTAs/SM.
//   z=0: Q (3-product)  z=1: K (3-product)  z=2: V (2-product)
// ===========================================================================
#define QA_TILE (128*PITCHB)          // 18432
#define QB_TILE (64*PITCHB)           // 9216
#define Q_STAGE (2*QA_TILE + 2*QB_TILE)  // 55296
#define SMEMQ   (2*Q_STAGE)           // 110592

__global__ __launch_bounds__(256, 2)
void gemm_qkv(const __half* __restrict__ xh, const __half* __restrict__ xl,
              const __half* __restrict__ Wqh, const __half* __restrict__ Wql,
              const __half* __restrict__ Wkh, const __half* __restrict__ Wkl,
              const __half* __restrict__ Wvh, const __half* __restrict__ Wvl,
              const float* __restrict__ bq, const float* __restrict__ bk,
              const float* __restrict__ bv,
              float* __restrict__ Qf, float* __restrict__ Kf, float* __restrict__ Vf,
              __half* __restrict__ Qh, __half* __restrict__ Kh)
{
    extern __shared__ __align__(128) char dsm[];
    const int tid = threadIdx.x;
    const int wid = tid >> 5, lane = tid & 31;
    const int warp_m = wid & 3, warp_n = wid >> 2;     // 4 x 2
    const int m0 = blockIdx.y * 128, n0 = blockIdx.x * 64;
    const int z = blockIdx.z;
    const bool p3 = (z != 2);

    const __half* Bh_ = (z == 0) ? Wqh : (z == 1) ? Wkh : Wvh;
    const __half* Bl_ = (z == 0) ? Wql : (z == 1) ? Wkl : Wvl;
    const float*  bias = (z == 0) ? bq : (z == 1) ? bk : bv;
    float* Cf  = (z == 0) ? Qf : (z == 1) ? Kf : Vf;
    __half* Ch = (z == 0) ? Qh : (z == 1) ? Kh : nullptr;

    const __half* pA0 = xh + (size_t)m0 * DD;
    const __half* pA1 = xl + (size_t)m0 * DD;
    const __half* pB0 = Bh_ + (size_t)n0 * DD;
    const __half* pB1 = Bl_ + (size_t)n0 * DD;

    const uint32_t sb = s2u(dsm);

    // per chunk: Ah 1024 + Al 1024 + Bh 512 + Bl 512 = 3072 CP16 -> 12/thread
    auto issue = [&](int c, int s){
        const int kc0 = c * 64;
        const uint32_t st = sb + s * Q_STAGE;
        #pragma unroll
        for (int i = 0; i < 12; i++){
            int idx = tid + i * 256;
            if (idx < 2048){
                int t = idx >> 10;               // 0=Ah 1=Al
                int rem = idx & 1023;
                int r = rem >> 3, q = rem & 7;
                CP16(st + t * QA_TILE + r * PITCHB + q * 16,
                     (t ? pA1 : pA0) + (size_t)r * DD + kc0 + q * 8);
            } else {
                int rem2 = idx - 2048;
                int t2 = rem2 >> 9;              // 0=Bh 1=Bl
                if (t2 == 1 && !p3) continue;
                int rem = rem2 & 511;
                int r = rem >> 3, q = rem & 7;
                CP16(st + 2*QA_TILE + t2 * QB_TILE + r * PITCHB + q * 16,
                     (t2 ? pB1 : pB0) + (size_t)r * DD + kc0 + q * 8);
            }
        }
        CP_COMMIT();
    };

    const int lrow = lane & 15, lph = lane >> 4;
    uint32_t aA[2], aB[2];
    #pragma unroll
    for (int f = 0; f < 2; f++)
        aA[f] = sb + (warp_m*32 + f*16 + lrow) * PITCHB + lph * 16;
    #pragma unroll
    for (int p = 0; p < 2; p++)
        aB[p] = sb + 2*QA_TILE + (warp_n*32 + p*16 + lrow) * PITCHB + lph * 16;

    float acc[2][4][4];
    uint32_t accl[2][4][2];
    #pragma unroll
    for (int f = 0; f < 2; f++)
        #pragma unroll
        for (int b = 0; b < 4; b++){
            #pragma unroll
            for (int j = 0; j < 4; j++) acc[f][b][j] = 0.f;
            accl[f][b][0] = 0u; accl[f][b][1] = 0u;
        }

    const int NC = DD / 64;
    issue(0, 0);
    issue(1, 1);

    for (int c = 0; c < NC; c++){
        if (c < NC - 1) CP_WAIT1(); else CP_WAIT0();
        __syncthreads();

        const uint32_t so = (c & 1) * Q_STAGE;
        #pragma unroll
        for (int ks = 0; ks < 4; ks++){
            const uint32_t ko = ks * 32;
            uint32_t ah[2][4], al[2][4], bh[2][4], bl[2][4];
            #pragma unroll
            for (int f = 0; f < 2; f++){
                LDSM4(ah[f][0],ah[f][1],ah[f][2],ah[f][3], aA[f] + so + ko);
                LDSM4(al[f][0],al[f][1],al[f][2],al[f][3], aA[f] + so + ko + QA_TILE);
            }
            #pragma unroll
            for (int p = 0; p < 2; p++){
                LDSM4(bh[p][0],bh[p][1],bh[p][2],bh[p][3], aB[p] + so + ko);
                if (p3)
                    LDSM4(bl[p][0],bl[p][1],bl[p][2],bl[p][3], aB[p] + so + ko + QB_TILE);
            }
            #pragma unroll
            for (int f = 0; f < 2; f++)
                #pragma unroll
                for (int p = 0; p < 2; p++)
                    #pragma unroll
                    for (int nb = 0; nb < 2; nb++){
                        float* cc = acc[f][p*2+nb];
                        uint32_t* cl = accl[f][p*2+nb];
                        MMAF32(cc, ah[f][0],ah[f][1],ah[f][2],ah[f][3],
                               bh[p][nb], bh[p][nb+2]);
                        MMAF16(cl, al[f][0],al[f][1],al[f][2],al[f][3],
                               bh[p][nb], bh[p][nb+2]);
                        if (p3)
                            MMAF16(cl, ah[f][0],ah[f][1],ah[f][2],ah[f][3],
                                   bl[p][nb], bl[p][nb+2]);
                    }
        }
        __syncthreads();                 // stage fully read before refill
        if (c + 2 < NC) issue(c + 2, c & 1);
    }

    // ---- epilogue: merge -> staging smem [128][68] -> global ----
    float* stg = (float*)dsm;
    const int erow = lane >> 2, ecol2 = (lane & 3) * 2;
    #pragma unroll
    for (int f = 0; f < 2; f++)
        #pragma unroll
        for (int p = 0; p < 2; p++)
            #pragma unroll
            for (int nb = 0; nb < 2; nb++){
                int r  = warp_m*32 + f*16 + erow;
                int cl = warp_n*32 + p*16 + nb*8 + ecol2;
                float* cc = acc[f][p*2+nb];
                uint32_t* lr = accl[f][p*2+nb];
                float2 w0 = __half22float2(*reinterpret_cast<__half2*>(&lr[0]));
                float2 w1 = __half22float2(*reinterpret_cast<__half2*>(&lr[1]));
                *(float2*)&stg[r*68 + cl] =
                    make_float2(cc[0] + w0.x*LINV, cc[1] + w0.y*LINV);
                *(float2*)&stg[(r+8)*68 + cl] =
                    make_float2(cc[2] + w1.x*LINV, cc[3] + w1.y*LINV);
            }
    __syncthreads();

    #pragma unroll
    for (int i = 0; i < 32; i++){
        int idx = tid + i * 256;
        int j = idx & 63, m = idx >> 6;
        float v = stg[m*68 + j] + bias[n0 + j];
        size_t o = (size_t)(m0 + m) * DD + n0 + j;
        Cf[o] = v;
        if (p3) Ch[o] = __float2half(v);
    }
}

// ===========================================================================
// gemm_s: cheap scores. CTA 128x128, 8 warps (4m x 2n), warp tile 32x64.
// hi planes only -> stage = A+B = 36 KB, 3 stages = 108 KB -> 2 CTAs/SM.
// ===========================================================================
#define S_TILE  (128*PITCHB)          // 18432
#define S_STAGE (2*S_TILE)            // 36864
#define SMEMS   (3*S_STAGE)           // 110592

__global__ __launch_bounds__(256, 2)
void gemm_s(const __half* __restrict__ Qh, const __half* __restrict__ Kh,
            __half* __restrict__ Sout)
{
    extern __shared__ __align__(128) char dsm[];
    const int tid = threadIdx.x;
    const int wid = tid >> 5, lane = tid & 31;
    const int warp_m = wid & 3, warp_n = wid >> 2;
    const int m0 = blockIdx.y * 128, n0 = blockIdx.x * 128, z = blockIdx.z;

    const __half* pA = Qh + (size_t)z * SS * DD + (size_t)m0 * DD;
    const __half* pB = Kh + (size_t)z * SS * DD + (size_t)n0 * DD;

    const uint32_t sb = s2u(dsm);

    auto issue = [&](int c, int s){
        const int kc0 = c * 64;
        const uint32_t st = sb + s * S_STAGE;
        #pragma unroll
        for (int i = 0; i < 8; i++){
            int idx = tid + i * 256;
            int hi = idx >> 10;
            int rem = idx & 1023;
            int r = rem >> 3, q = rem & 7;
            CP16(st + hi * S_TILE + r * PITCHB + q * 16,
                 (hi ? pB : pA) + (size_t)r * DD + kc0 + q * 8);
        }
        CP_COMMIT();
    };

    const int lrow = lane & 15, lph = lane >> 4;
    uint32_t aA[2], aB[4];
    #pragma unroll
    for (int f = 0; f < 2; f++)
        aA[f] = sb + (warp_m*32 + f*16 + lrow) * PITCHB + lph * 16;
    #pragma unroll
    for (int p = 0; p < 4; p++)
        aB[p] = sb + S_TILE + (warp_n*64 + p*16 + lrow) * PITCHB + lph * 16;

    float acc[2][8][4];
    #pragma unroll
    for (int f = 0; f < 2; f++)
        #pragma unroll
        for (int b = 0; b < 8; b++)
            #pragma unroll
            for (int j = 0; j < 4; j++) acc[f][b][j] = 0.f;

    const int NC = DD / 64;
    issue(0, 0);
    issue(1, 1);

    for (int c = 0; c < NC; c++){
        if (c < NC - 1) CP_WAIT1(); else CP_WAIT0();
        __syncthreads();
        if (c + 2 < NC) issue(c + 2, (c + 2) % 3);

        const uint32_t so = (c % 3) * S_STAGE;
        #pragma unroll
        for (int ks = 0; ks < 4; ks++){
            const uint32_t ko = ks * 32;
            uint32_t ah[2][4], bh[4][4];
            #pragma unroll
            for (int f = 0; f < 2; f++)
                LDSM4(ah[f][0],ah[f][1],ah[f][2],ah[f][3], aA[f] + so + ko);
            #pragma unroll
            for (int p = 0; p < 4; p++)
                LDSM4(bh[p][0],bh[p][1],bh[p][2],bh[p][3], aB[p] + so + ko);
            #pragma unroll
            for (int f = 0; f < 2; f++)
                #pragma unroll
                for (int p = 0; p < 4; p++)
                    #pragma unroll
                    for (int nb = 0; nb < 2; nb++)
                        MMAF32(acc[f][p*2+nb], ah[f][0],ah[f][1],ah[f][2],ah[f][3],
                               bh[p][nb], bh[p][nb+2]);
        }
    }
    __syncthreads();

    float* stg = (float*)dsm;
    const int erow = lane >> 2, ecol2 = (lane & 3) * 2;
    #pragma unroll
    for (int f = 0; f < 2; f++)
        #pragma unroll
        for (int p = 0; p < 4; p++)
            #pragma unroll
            for (int nb = 0; nb < 2; nb++){
                int r  = warp_m*32 + f*16 + erow;
                int cl = warp_n*64 + p*16 + nb*8 + ecol2;
                float* cc = acc[f][p*2+nb];
                *(float2*)&stg[r*132 + cl]     = make_float2(cc[0], cc[1]);
                *(float2*)&stg[(r+8)*132 + cl] = make_float2(cc[2], cc[3]);
            }
    __syncthreads();

    #pragma unroll
    for (int i = 0; i < 32; i++){
        int idx = tid + i * 256;
        int j2 = idx & 63, m = idx >> 6;
        float v0 = stg[m*132 + 2*j2], v1 = stg[m*132 + 2*j2 + 1];
        ((__half2*)Sout)[((size_t)z * SS * SS + (size_t)(m0 + m) * SS + n0) / 2 + j2] =
            __floats2half2_rn(v0, v1);
    }
}

// ---------------------------------------------------------------------------
__global__ __launch_bounds__(256)
void conv_x(const float* __restrict__ in, __half* __restrict__ oh,
            __half* __restrict__ ol)
{
    int i = blockIdx.x * 256 + threadIdx.x;
    float4 v = ((const float4*)in)[i];
    __half h0,h1,h2,h3,l0,l1,l2,l3;
    split2h(v.x,h0,l0); split2h(v.y,h1,l1); split2h(v.z,h2,l2); split2h(v.w,h3,l3);
    __half2* H = (__half2*)oh;  __half2* L = (__half2*)ol;
    H[i*2+0] = __halves2half2(h0,h1);  H[i*2+1] = __halves2half2(h2,h3);
    L[i*2+0] = __halves2half2(l0,l1);  L[i*2+1] = __halves2half2(l2,l3);
}

__global__ __launch_bounds__(256)
void conv_w(const float* __restrict__ Wq, const float* __restrict__ Wk,
            const float* __restrict__ Wv)
{
    int i = blockIdx.x * 256 + threadIdx.x;
    int z = blockIdx.y;
    const float* in = (z == 0) ? Wq : (z == 1) ? Wk : Wv;
    __half* oh = (z == 0) ? g_Wqh : (z == 1) ? g_Wkh : g_Wvh;
    __half* ol = (z == 0) ? g_Wql : (z == 1) ? g_Wkl : g_Wvl;
    float4 v = ((const float4*)in)[i];
    __half h0,h1,h2,h3,l0,l1,l2,l3;
    split2h(v.x,h0,l0); split2h(v.y,h1,l1); split2h(v.z,h2,l2); split2h(v.w,h3,l3);
    __half2* H = (__half2*)oh;  __half2* L = (__half2*)ol;
    H[i*2+0] = __halves2half2(h0,h1);  H[i*2+1] = __halves2half2(h2,h3);
    L[i*2+0] = __halves2half2(l0,l1);  L[i*2+1] = __halves2half2(l2,l3);
}

// ---------------------------------------------------------------------------
// Fused softmax-select-refine-gather. One CTA (256 thr) per query row.
// ---------------------------------------------------------------------------
__global__ __launch_bounds__(256)
void attn_k(const float* __restrict__ Q, const float* __restrict__ K,
            const float* __restrict__ V, float* __restrict__ out)
{
    const int g = blockIdx.x;
    const int b = g >> 11;
    const __half2* srow = (const __half2*)(g_S + (size_t)g * SS);
    const int tid = threadIdx.x;
    const int lane = tid & 31, w = tid >> 5;

    __shared__ float red[8];
    __shared__ int   s_idx[SS];
    __shared__ float s_p[SS];
    __shared__ int   s_cnt;

    float lv[8];
    float mx = -3.4e38f;
    #pragma unroll
    for (int i = 0; i < 4; i++){
        float2 v2 = __half22float2(srow[tid + i*256]);
        lv[2*i] = v2.x; lv[2*i+1] = v2.y;
        mx = fmaxf(mx, fmaxf(v2.x, v2.y));
    }
    #pragma unroll
    for (int o = 16; o; o >>= 1) mx = fmaxf(mx, __shfl_xor_sync(0xffffffffu, mx, o));
    if (lane == 0) red[w] = mx;
    if (tid == 0) s_cnt = 0;
    __syncthreads();
    float m = red[0];
    #pragma unroll
    for (int i = 1; i < 8; i++) m = fmaxf(m, red[i]);

    const float thr = m - 18.0f;
    #pragma unroll
    for (int i = 0; i < 4; i++){
        if (lv[2*i] > thr){
            int pos = atomicAdd(&s_cnt, 1);
            s_idx[pos] = 2*(tid + i*256);
        }
        if (lv[2*i+1] > thr){
            int pos = atomicAdd(&s_cnt, 1);
            s_idx[pos] = 2*(tid + i*256) + 1;
        }
    }
    __syncthreads();
    const int nc = s_cnt;

    const float* qr = Q + (size_t)g * DD;
    for (int j = w; j < nc; j += 8){
        const float* kr = K + ((size_t)(b << 11) + s_idx[j]) * DD;
        float a = 0.f;
        #pragma unroll 8
        for (int d = lane; d < DD; d += 32) a += qr[d] * kr[d];
        #pragma unroll
        for (int o = 16; o; o >>= 1) a += __shfl_xor_sync(0xffffffffu, a, o);
        if (lane == 0) s_p[j] = expf(a - m);
    }
    __syncthreads();

    float Z = 0.f;
    for (int j = 0; j < nc; j++) Z += s_p[j];
    const float invZ = 1.0f / Z;

    float4 o4 = make_float4(0.f, 0.f, 0.f, 0.f);
    for (int j = 0; j < nc; j++){
        const float pj = s_p[j];
        float4 vv = ((const float4*)(V + ((size_t)(b << 11) + s_idx[j]) * DD))[tid];
        o4.x += pj * vv.x; o4.y += pj * vv.y;
        o4.z += pj * vv.z; o4.w += pj * vv.w;
    }
    o4.x *= invZ; o4.y *= invZ; o4.z *= invZ; o4.w *= invZ;
    ((float4*)(out + (size_t)g * DD))[tid] = o4;
}

// ---------------------------------------------------------------------------
extern "C" void kernel_launch(void* const* d_in, const int* in_sizes, int n_in,
                              void* d_out, int out_size)
{
    const float* x  = (const float*)d_in[0];
    const float* Wq = (const float*)d_in[1];
    const float* bq = (const float*)d_in[2];
    const float* Wk = (const float*)d_in[3];
    const float* bk = (const float*)d_in[4];
    const float* Wv = (const float*)d_in[5];
    const float* bv = (const float*)d_in[6];
    float* out = (float*)d_out;

    __half *xh,*xl,*Wqh,*Wql,*Wkh,*Wkl,*Wvh,*Wvl,*Qh,*Kh,*Sp;
    float *Qf,*Kf,*Vf;
    cudaGetSymbolAddress((void**)&xh,  g_xh);  cudaGetSymbolAddress((void**)&xl,  g_xl);
    cudaGetSymbolAddress((void**)&Wqh, g_Wqh); cudaGetSymbolAddress((void**)&Wql, g_Wql);
    cudaGetSymbolAddress((void**)&Wkh, g_Wkh); cudaGetSymbolAddress((void**)&Wkl, g_Wkl);
    cudaGetSymbolAddress((void**)&Wvh, g_Wvh); cudaGetSymbolAddress((void**)&Wvl, g_Wvl);
    cudaGetSymbolAddress((void**)&Qf,  g_Qf);  cudaGetSymbolAddress((void**)&Kf,  g_Kf);
    cudaGetSymbolAddress((void**)&Vf,  g_Vf);
    cudaGetSymbolAddress((void**)&Qh,  g_Qh);  cudaGetSymbolAddress((void**)&Kh,  g_Kh);
    cudaGetSymbolAddress((void**)&Sp,  g_S);

    cudaFuncSetAttribute(gemm_qkv, cudaFuncAttributeMaxDynamicSharedMemorySize, SMEMQ);
    cudaFuncSetAttribute(gemm_s,   cudaFuncAttributeMaxDynamicSharedMemorySize, SMEMS);

    // 0) splits
    conv_x<<<M1*DD/4/256, 256>>>(x, xh, xl);
    conv_w<<<dim3(DD*DD/4/256, 3), 256>>>(Wq, Wk, Wv);

    // 1) merged projections (z: 0=Q, 1=K, 2=V), CTA tile 128x64
    dim3 gp(DD/64, M1/128, 3);
    gemm_qkv<<<gp, 256, SMEMQ>>>(xh, xl, Wqh, Wql, Wkh, Wkl, Wvh, Wvl,
                                 bq, bk, bv, Qf, Kf, Vf, Qh, Kh);

    // 2) cheap scores
    dim3 gs(SS/128, SS/128, BB);
    gemm_s<<<gs, 256, SMEMS>>>(Qh, Kh, Sp);

    // 3) fused softmax-select-refine-gather
    attn_k<<<M1, 256>>>(Qf, Kf, Vf, out);
}